// round 10
// baseline (speedup 1.0000x reference)
#include <cuda_runtime.h>
#include <cuda_fp16.h>
#include <math.h>
#include <stdint.h>

// ---------------- problem constants ----------------
#define IN_DIM   768
#define HID      3072
#define BATCH    64
#define NCLS     6
#define NUM_PATCH 576
#define ATOMS    5
#define SEQ      (NCLS + NUM_PATCH)          // 582
#define M_PATCH  (BATCH * NUM_PATCH)         // 36864
#define M_CLS    (BATCH * NCLS)              // 384
#define M_ALL    (M_PATCH + M_CLS)           // 37248

// ---------------- device scratch (plain fp16 operands) ----------------
__device__ __half g_xh  [(size_t)M_ALL * IN_DIM];
__device__ __half g_w1t [(size_t)HID * IN_DIM];
__device__ __half g_hid [(size_t)M_ALL * HID];
__device__ __half g_w2t [(size_t)IN_DIM * HID];
__device__ __half g_wint [(size_t)ATOMS * HID * IN_DIM];
__device__ __half g_hm  [(size_t)ATOMS * M_CLS * HID];
__device__ __half g_woutt[(size_t)ATOMS * IN_DIM * HID];
__device__ float g_allo[(size_t)ATOMS * ATOMS * M_CLS * IN_DIM];
__device__ float g_e0  [(size_t)M_CLS * IN_DIM];

__device__ __forceinline__ float gelu_f(float v) {
    return 0.5f * v * (1.0f + erff(v * 0.7071067811865476f));
}

// ---------------- PTX helpers (baseline sm_80+ only) ----------------
__device__ __forceinline__ uint32_t smem_u32(const void* p) {
    uint32_t a;
    asm("{ .reg .u64 t; cvta.to.shared.u64 t, %1; cvt.u32.u64 %0, t; }" : "=r"(a) : "l"(p));
    return a;
}
__device__ __forceinline__ void cp16(uint32_t d, const void* s) {
    asm volatile("cp.async.cg.shared.global [%0], [%1], 16;" :: "r"(d), "l"(s));
}
#define CP_COMMIT()  asm volatile("cp.async.commit_group;" ::: "memory")
#define CP_WAIT(n)   asm volatile("cp.async.wait_group %0;" :: "n"(n) : "memory")

__device__ __forceinline__ void ldsm_x4(uint32_t& r0, uint32_t& r1, uint32_t& r2, uint32_t& r3,
                                        uint32_t addr) {
    asm volatile("ldmatrix.sync.aligned.m8n8.x4.shared.b16 {%0,%1,%2,%3}, [%4];"
                 : "=r"(r0), "=r"(r1), "=r"(r2), "=r"(r3) : "r"(addr));
}
__device__ __forceinline__ void mma_f16(float& c0, float& c1, float& c2, float& c3,
                                        uint32_t a0, uint32_t a1, uint32_t a2, uint32_t a3,
                                        uint32_t b0, uint32_t b1) {
    asm volatile("mma.sync.aligned.m16n8k16.row.col.f32.f16.f16.f32 "
                 "{%0,%1,%2,%3}, {%4,%5,%6,%7}, {%8,%9}, {%0,%1,%2,%3};"
                 : "+f"(c0), "+f"(c1), "+f"(c2), "+f"(c3)
                 : "r"(a0), "r"(a1), "r"(a2), "r"(a3), "r"(b0), "r"(b1));
}
__device__ __forceinline__ uint32_t sw128(uint32_t off) {
    return off ^ ((off >> 3) & 0x70);
}

// ---------------- HMMA GEMM core ----------------
// CTA tile 128x128, BK=64, 4 warps as 2(M) x 2(N), warp tile 64x64.
// 3-stage cp.async, 128 threads, 2 CTAs/SM, fragment double-buffering.
#define BM 128
#define BN 128
#define BK 64
#define STAGES 3
#define STG_BYTES (BM * 128)                     // 16 KB per operand per stage
#define SMEM_DYN (STAGES * 2 * STG_BYTES)        // 96 KB
#define NTHREADS 128

#define A_NBX    (HID / BN)                      // 24
#define A_NBIG   (A_NBX * (M_ALL / BM))          // 6984
#define A_NSMALL (A_NBX * (M_CLS / BM) * ATOMS)  // 360
#define A_TOTAL  (A_NBIG + A_NSMALL)
#define B_NBX    (IN_DIM / BN)                   // 6
#define B_NBIG   (B_NBX * (M_ALL / BM))          // 1746
#define B_NSMALL (B_NBX * (M_CLS / BM) * ATOMS * ATOMS)  // 450
#define B_TOTAL  (B_NBIG + B_NSMALL)

// PHASE 0: d->h GELU, fp16 output (GEMM1 + GEMM3);  K = IN_DIM
// PHASE 1: h->d, fp32 output (GEMM2 scatter + GEMM4); K = HID
template<int PHASE>
__global__ __launch_bounds__(NTHREADS, 2)
void mlp_gemm(const __half* __restrict__ xh,
              const __half* __restrict__ wBig,
              const __half* __restrict__ wSmall,
              const __half* __restrict__ hm,
              const float* __restrict__ biasBig,
              const float* __restrict__ biasSmall,
              __half* __restrict__ outBigH,
              __half* __restrict__ outSmallH,
              float* __restrict__ outBigF,
              float* __restrict__ outE0,
              float* __restrict__ outSmallF)
{
    extern __shared__ char smem[];
    const uint32_t sb = smem_u32(smem);
    const int tid  = threadIdx.x;
    const int wid  = tid >> 5, lane = tid & 31;
    const int wm   = wid >> 1;               // 0..1  (M, 64 rows)
    const int wn   = wid & 1;                // 0..1  (N, 64 cols)

    const int bi = blockIdx.x;
    const int K  = (PHASE == 0) ? IN_DIM : HID;
    const int C  = K >> 6;
    int bm, bn, sub;
    const __half* A;
    const __half* B;
    const float* bias;
    if (PHASE == 0) {
        if (bi < A_NBIG) {
            sub = 0;
            bm = (bi / A_NBX) * BM; bn = (bi % A_NBX) * BN;
            A = xh; B = wBig; bias = biasBig;
        } else {
            int r = bi - A_NBIG;
            int a = r / (A_NBX * (M_CLS / BM));
            r -= a * (A_NBX * (M_CLS / BM));
            sub = 1 + a;
            bm = (r / A_NBX) * BM; bn = (r % A_NBX) * BN;
            A = xh + (size_t)M_PATCH * IN_DIM;
            B = wSmall + (size_t)a * HID * IN_DIM;
            bias = biasSmall + (size_t)a * HID;
        }
    } else {
        if (bi < B_NBIG) {
            sub = 0;
            bm = (bi / B_NBX) * BM; bn = (bi % B_NBX) * BN;
            A = xh; B = wBig; bias = biasBig;
        } else {
            int r = bi - B_NBIG;
            int z = r / (B_NBX * (M_CLS / BM));
            r -= z * (B_NBX * (M_CLS / BM));
            sub = 1 + z;
            bm = (r / B_NBX) * BM; bn = (r % B_NBX) * BN;
            int a = z / ATOMS, o = z % ATOMS;
            A = hm + (size_t)a * M_CLS * HID;
            B = wSmall + (size_t)o * IN_DIM * HID;
            bias = biasSmall + (size_t)o * IN_DIM;
        }
    }

    const __half* aG0 = A + (size_t)bm * K;
    const __half* bG0 = B + (size_t)bn * K;

    auto loadChunk = [&](int c) {
        const int slot = c % STAGES;
        const uint32_t aS = sb + (uint32_t)slot * (2 * STG_BYTES);
        const uint32_t bS = aS + STG_BYTES;
        const __half* aG = aG0 + c * BK;
        const __half* bG = bG0 + c * BK;
        #pragma unroll
        for (int t = 0; t < 8; t++) {
            int i = t * NTHREADS + tid;
            int row = i >> 3, g = i & 7;
            uint32_t off = (uint32_t)(row * 128 + g * 16);
            cp16(aS + sw128(off), aG + (size_t)row * K + g * 8);
        }
        #pragma unroll
        for (int t = 0; t < 8; t++) {
            int i = t * NTHREADS + tid;
            int row = i >> 3, g = i & 7;
            uint32_t off = (uint32_t)(row * 128 + g * 16);
            cp16(bS + sw128(off), bG + (size_t)row * K + g * 8);
        }
        CP_COMMIT();
    };

    float acc[4][8][4];
    #pragma unroll
    for (int i = 0; i < 4; i++)
        #pragma unroll
        for (int j = 0; j < 8; j++)
            #pragma unroll
            for (int q = 0; q < 4; q++) acc[i][j][q] = 0.0f;

    loadChunk(0);
    loadChunk(1);

    const int aRow = wm * 64 + (lane & 15);
    const int aCol = (lane >> 4) * 16;
    const int bRow = wn * 64 + ((lane >> 4) & 1) * 8 + (lane & 7);
    const int bCol = ((lane >> 3) & 1) * 16;

    // double-buffered fragments
    uint32_t af[2][4][4];
    uint32_t bf[2][8][2];

    auto loadFrags = [&](uint32_t aS, uint32_t bS, int kk, int buf) {
        #pragma unroll
        for (int mt = 0; mt < 4; mt++) {
            uint32_t off = (uint32_t)((aRow + mt * 16) * 128 + kk * 32 + aCol);
            ldsm_x4(af[buf][mt][0], af[buf][mt][1], af[buf][mt][2], af[buf][mt][3],
                    aS + sw128(off));
        }
        #pragma unroll
        for (int pr = 0; pr < 4; pr++) {
            uint32_t off = (uint32_t)((bRow + pr * 16) * 128 + kk * 32 + bCol);
            uint32_t r0, r1, r2, r3;
            ldsm_x4(r0, r1, r2, r3, bS + sw128(off));
            bf[buf][pr * 2 + 0][0] = r0; bf[buf][pr * 2 + 0][1] = r1;
            bf[buf][pr * 2 + 1][0] = r2; bf[buf][pr * 2 + 1][1] = r3;
        }
    };

    for (int c = 0; c < C; c++) {
        if (c + 2 < C) { CP_WAIT(1); } else { CP_WAIT(0); }
        __syncthreads();
        if (c + 2 < C) loadChunk(c + 2);

        const int slot = c % STAGES;
        const uint32_t aS = sb + (uint32_t)slot * (2 * STG_BYTES);
        const uint32_t bS = aS + STG_BYTES;

        loadFrags(aS, bS, 0, 0);
        #pragma unroll
        for (int kk = 0; kk < 4; kk++) {
            const int cur = kk & 1;
            if (kk < 3) loadFrags(aS, bS, kk + 1, cur ^ 1);
            #pragma unroll
            for (int mt = 0; mt < 4; mt++)
                #pragma unroll
                for (int nt = 0; nt < 8; nt++)
                    mma_f16(acc[mt][nt][0], acc[mt][nt][1], acc[mt][nt][2], acc[mt][nt][3],
                            af[cur][mt][0], af[cur][mt][1], af[cur][mt][2], af[cur][mt][3],
                            bf[cur][nt][0], bf[cur][nt][1]);
        }
    }

    // ---------------- epilogue ----------------
    const int q = lane & 3;
    #pragma unroll
    for (int mt = 0; mt < 4; mt++) {
        #pragma unroll
        for (int h = 0; h < 2; h++) {
            const int rowg = bm + wm * 64 + mt * 16 + (lane >> 2) + h * 8;
            __half* rpH = nullptr;
            float*  rpF = nullptr;
            if (PHASE == 0) {
                rpH = (sub == 0 ? outBigH : outSmallH + (size_t)(sub - 1) * M_CLS * HID)
                      + (size_t)rowg * HID;
            } else if (sub == 0) {
                if (rowg < M_PATCH) {
                    int bb = rowg / NUM_PATCH, p = rowg - bb * NUM_PATCH;
                    rpF = outBigF + (size_t)(bb * SEQ + NCLS + p) * IN_DIM;
                } else {
                    rpF = outE0 + (size_t)(rowg - M_PATCH) * IN_DIM;
                }
            } else {
                rpF = outSmallF + (size_t)(sub - 1) * M_CLS * IN_DIM + (size_t)rowg * IN_DIM;
            }
            #pragma unroll
            for (int nt = 0; nt < 8; nt++) {
                const int col = bn + wn * 64 + nt * 8 + q * 2;
                float v0 = acc[mt][nt][h * 2 + 0] + bias[col];
                float v1 = acc[mt][nt][h * 2 + 1] + bias[col + 1];
                if (PHASE == 0) {
                    v0 = gelu_f(v0); v1 = gelu_f(v1);
                    __half2 hh; hh.x = __float2half(v0); hh.y = __float2half(v1);
                    *reinterpret_cast<__half2*>(rpH + col) = hh;
                } else {
                    *reinterpret_cast<float2*>(rpF + col) = make_float2(v0, v1);
                }
            }
        }
    }
}

// ---------------- fused conversion kernel (single launch) ----------------
#define CX_BLK   (M_ALL * IN_DIM / 4 / 256)            // 27936
#define WT_W1    (IN_DIM / 32 * (HID / 32))            // 2304
#define WT_W2    (HID / 32 * (IN_DIM / 32))            // 2304
#define WT_WIN   (WT_W1 * ATOMS)
#define WT_WOUT  (WT_W2 * ATOMS)
#define CONV_TOTAL (CX_BLK + WT_W1 + WT_W2 + WT_WIN + WT_WOUT)

__global__ __launch_bounds__(256)
void conv_all(const float* __restrict__ x,   __half* __restrict__ xh,
              const float* __restrict__ W1,  __half* __restrict__ w1t,
              const float* __restrict__ W2,  __half* __restrict__ w2t,
              const float* __restrict__ Win, __half* __restrict__ wint,
              const float* __restrict__ Wout,__half* __restrict__ woutt)
{
    int bi = blockIdx.x;
    if (bi < CX_BLK) {
        int idx = bi * 256 + threadIdx.x;            // units of 4 elems
        int m  = idx / (IN_DIM / 4);
        int kp = (idx - m * (IN_DIM / 4)) * 4;
        int src;
        if (m < M_PATCH) { int b = m / NUM_PATCH, p = m - b * NUM_PATCH; src = b * SEQ + NCLS + p; }
        else             { int rr = m - M_PATCH; int b = rr / NCLS, t = rr - b * NCLS; src = b * SEQ + t; }
        float4 vv = *reinterpret_cast<const float4*>(x + (size_t)src * IN_DIM + kp);
        __half2 h01; h01.x = __float2half(vv.x); h01.y = __float2half(vv.y);
        __half2 h23; h23.x = __float2half(vv.z); h23.y = __float2half(vv.w);
        uint2 pk; pk.x = *reinterpret_cast<uint32_t*>(&h01); pk.y = *reinterpret_cast<uint32_t*>(&h23);
        *reinterpret_cast<uint2*>(xh + (size_t)m * IN_DIM + kp) = pk;
        return;
    }
    bi -= CX_BLK;

    const float* W; __half* Wt; int K, N, tileIdx;
    if (bi < WT_W1)                   { W = W1;  Wt = w1t;  K = IN_DIM; N = HID;    tileIdx = bi; }
    else if ((bi -= WT_W1)  < WT_W2)  { W = W2;  Wt = w2t;  K = HID;    N = IN_DIM; tileIdx = bi; }
    else if ((bi -= WT_W2)  < WT_WIN) {
        int z = bi / WT_W1; tileIdx = bi - z * WT_W1;
        W = Win  + (size_t)z * IN_DIM * HID; Wt = wint  + (size_t)z * HID * IN_DIM;
        K = IN_DIM; N = HID;
    } else {
        bi -= WT_WIN;
        int z = bi / WT_W2; tileIdx = bi - z * WT_W2;
        W = Wout + (size_t)z * HID * IN_DIM; Wt = woutt + (size_t)z * IN_DIM * HID;
        K = HID; N = IN_DIM;
    }

    __shared__ float t[32][33];
    const int ktiles = K / 32;
    int k0 = (tileIdx % ktiles) * 32, n0 = (tileIdx / ktiles) * 32;
    int tx = threadIdx.x & 31, ty = threadIdx.x >> 5;
    #pragma unroll
    for (int i = 0; i < 4; i++)
        t[ty + i * 8][tx] = W[(size_t)(k0 + ty + i * 8) * N + n0 + tx];
    __syncthreads();
    // vectorized half2 stores: 512 k-pair items = 32 n rows x 16 pairs
    #pragma unroll
    for (int it = 0; it < 2; it++) {
        int item = it * 256 + threadIdx.x;
        int n  = n0 + (item >> 4);
        int kp = (item & 15) * 2;
        __half2 hv;
        hv.x = __float2half(t[kp][item >> 4]);
        hv.y = __float2half(t[kp + 1][item >> 4]);
        *reinterpret_cast<__half2*>(Wt + (size_t)n * K + k0 + kp) = hv;
    }
}

// ---------------- gating + expert mixing ----------------
__global__ __launch_bounds__(256)
void gate_mix_kernel(const float* __restrict__ x,
                     const float* __restrict__ Wg,
                     const float* __restrict__ e0,
                     const float* __restrict__ allo,
                     float* __restrict__ out)
{
    const int n = blockIdx.x;
    const int b = n / NCLS;
    const int t = n - b * NCLS;
    const int a = t % ATOMS;

    __shared__ float scls[IN_DIM];
    __shared__ float slog[6];

    const float* crow = x + (size_t)(b * SEQ + t) * IN_DIM;
    for (int i = threadIdx.x; i < IN_DIM; i += 256) scls[i] = crow[i];
    __syncthreads();

    const int w = threadIdx.x >> 5, lane = threadIdx.x & 31;
    if (w < 6) {
        const float* wg = Wg + (size_t)t * IN_DIM * 6;
        float s = 0.0f;
        for (int d = lane; d < IN_DIM; d += 32)
            s = fmaf(scls[d], wg[(size_t)d * 6 + w], s);
        #pragma unroll
        for (int off = 16; off > 0; off >>= 1)
            s += __shfl_down_sync(0xffffffffu, s, off);
        if (lane == 0) slog[w] = s;
    }
    __syncthreads();

    float l[6];
    #pragma unroll
    for (int j = 0; j < 6; j++) l[j] = slog[j];
    int i0 = 0;
    #pragma unroll
    for (int j = 1; j < 6; j++) if (l[j] > l[i0]) i0 = j;
    int i1 = (i0 == 0) ? 1 : 0;
    #pragma unroll
    for (int j = 0; j < 6; j++) if (j != i0 && l[j] > l[i1]) i1 = j;
    float p1 = expf(l[i1] - l[i0]);
    float inv = 1.0f / (1.0f + p1);
    float w0 = inv, w1 = p1 * inv;

    const float* e0row = e0 + (size_t)n * IN_DIM;
    const float* r0 = (i0 == 0) ? e0row
        : allo + ((size_t)(a * ATOMS + (i0 - 1)) * M_CLS + n) * IN_DIM;
    const float* r1 = (i1 == 0) ? e0row
        : allo + ((size_t)(a * ATOMS + (i1 - 1)) * M_CLS + n) * IN_DIM;

    float* orow = out + (size_t)(b * SEQ + t) * IN_DIM;
    for (int c = threadIdx.x; c < IN_DIM; c += 256)
        orow[c] = w0 * r0[c] + w1 * r1[c];
}

// ---------------- launch ----------------
extern "C" void kernel_launch(void* const* d_in, const int* in_sizes, int n_in,
                              void* d_out, int out_size)
{
    const float* x     = (const float*)d_in[0];
    const float* W1    = (const float*)d_in[1];
    const float* b1    = (const float*)d_in[2];
    const float* W2    = (const float*)d_in[3];
    const float* b2    = (const float*)d_in[4];
    const float* W_in  = (const float*)d_in[5];
    const float* b_in  = (const float*)d_in[6];
    const float* W_out = (const float*)d_in[7];
    const float* b_out = (const float*)d_in[8];
    const float* Wg    = (const float*)d_in[9];
    float* out = (float*)d_out;

    static __half *xh = nullptr, *w1t, *hid, *w2t, *wint, *hm, *woutt;
    static float *allo, *e0;
    if (!xh) {
        cudaGetSymbolAddress((void**)&xh,    g_xh);
        cudaGetSymbolAddress((void**)&w1t,   g_w1t);
        cudaGetSymbolAddress((void**)&hid,   g_hid);
        cudaGetSymbolAddress((void**)&w2t,   g_w2t);
        cudaGetSymbolAddress((void**)&wint,  g_wint);
        cudaGetSymbolAddress((void**)&hm,    g_hm);
        cudaGetSymbolAddress((void**)&woutt, g_woutt);
        cudaGetSymbolAddress((void**)&allo,  g_allo);
        cudaGetSymbolAddress((void**)&e0,    g_e0);
        cudaFuncSetAttribute((const void*)mlp_gemm<0>,
                             cudaFuncAttributeMaxDynamicSharedMemorySize, SMEM_DYN);
        cudaFuncSetAttribute((const void*)mlp_gemm<1>,
                             cudaFuncAttributeMaxDynamicSharedMemorySize, SMEM_DYN);
    }

    // launch 1: all conversions fused
    conv_all<<<CONV_TOTAL, 256>>>(x, xh, W1, w1t, W2, w2t, W_in, wint, W_out, woutt);

    // launch 2: phase A (GEMM1 + GEMM3)
    mlp_gemm<0><<<A_TOTAL, NTHREADS, SMEM_DYN>>>(
        xh, w1t, wint, nullptr, b1, b_in,
        hid, hm, nullptr, nullptr, nullptr);

    // launch 3: phase B (GEMM2 + GEMM4)
    mlp_gemm<1><<<B_TOTAL, NTHREADS, SMEM_DYN>>>(
        hid, w2t, woutt, hm, b2, b_out,
        nullptr, nullptr, out, e0, allo);

    // launch 4: gating + mixing
    gate_mix_kernel<<<M_CLS, 256>>>(x, Wg, e0, allo, out);
}

// round 11
// speedup vs baseline: 1.0154x; 1.0154x over previous
#include <cuda_runtime.h>
#include <cuda_fp16.h>
#include <math.h>
#include <stdint.h>

// ---------------- problem constants ----------------
#define IN_DIM   768
#define HID      3072
#define BATCH    64
#define NCLS     6
#define NUM_PATCH 576
#define ATOMS    5
#define SEQ      (NCLS + NUM_PATCH)          // 582
#define M_PATCH  (BATCH * NUM_PATCH)         // 36864
#define M_CLS    (BATCH * NCLS)              // 384
#define M_ALL    (M_PATCH + M_CLS)           // 37248

// ---------------- device scratch (plain fp16 operands) ----------------
__device__ __half g_xh  [(size_t)M_ALL * IN_DIM];
__device__ __half g_w1t [(size_t)HID * IN_DIM];
__device__ __half g_hid [(size_t)M_ALL * HID];
__device__ __half g_w2t [(size_t)IN_DIM * HID];
__device__ __half g_wint [(size_t)ATOMS * HID * IN_DIM];
__device__ __half g_hm  [(size_t)ATOMS * M_CLS * HID];
__device__ __half g_woutt[(size_t)ATOMS * IN_DIM * HID];
__device__ float g_allo[(size_t)ATOMS * ATOMS * M_CLS * IN_DIM];
__device__ float g_e0  [(size_t)M_CLS * IN_DIM];

__device__ __forceinline__ float gelu_f(float v) {
    return 0.5f * v * (1.0f + erff(v * 0.7071067811865476f));
}

// ---------------- PTX helpers (baseline sm_80+ only) ----------------
__device__ __forceinline__ uint32_t smem_u32(const void* p) {
    uint32_t a;
    asm("{ .reg .u64 t; cvta.to.shared.u64 t, %1; cvt.u32.u64 %0, t; }" : "=r"(a) : "l"(p));
    return a;
}
__device__ __forceinline__ void cp16(uint32_t d, const void* s) {
    asm volatile("cp.async.cg.shared.global [%0], [%1], 16;" :: "r"(d), "l"(s));
}
#define CP_COMMIT()  asm volatile("cp.async.commit_group;" ::: "memory")
#define CP_WAIT(n)   asm volatile("cp.async.wait_group %0;" :: "n"(n) : "memory")

__device__ __forceinline__ void ldsm_x4(uint32_t& r0, uint32_t& r1, uint32_t& r2, uint32_t& r3,
                                        uint32_t addr) {
    asm volatile("ldmatrix.sync.aligned.m8n8.x4.shared.b16 {%0,%1,%2,%3}, [%4];"
                 : "=r"(r0), "=r"(r1), "=r"(r2), "=r"(r3) : "r"(addr));
}
__device__ __forceinline__ void mma_f16(float& c0, float& c1, float& c2, float& c3,
                                        uint32_t a0, uint32_t a1, uint32_t a2, uint32_t a3,
                                        uint32_t b0, uint32_t b1) {
    asm volatile("mma.sync.aligned.m16n8k16.row.col.f32.f16.f16.f32 "
                 "{%0,%1,%2,%3}, {%4,%5,%6,%7}, {%8,%9}, {%0,%1,%2,%3};"
                 : "+f"(c0), "+f"(c1), "+f"(c2), "+f"(c3)
                 : "r"(a0), "r"(a1), "r"(a2), "r"(a3), "r"(b0), "r"(b1));
}
__device__ __forceinline__ uint32_t sw128(uint32_t off) {
    return off ^ ((off >> 3) & 0x70);
}

// ---------------- HMMA GEMM core (R9 configuration — best measured) ----------------
// CTA tile 128x128, BK=64, 4 warps as 2(M) x 2(N), warp tile 64x64.
// 3-stage cp.async, 128 threads, 2 CTAs/SM.
#define BM 128
#define BN 128
#define BK 64
#define STAGES 3
#define STG_BYTES (BM * 128)                     // 16 KB per operand per stage
#define SMEM_DYN (STAGES * 2 * STG_BYTES)        // 96 KB
#define NTHREADS 128

#define A_NBX    (HID / BN)                      // 24
#define A_NBIG   (A_NBX * (M_ALL / BM))          // 6984
#define A_NSMALL (A_NBX * (M_CLS / BM) * ATOMS)  // 360
#define A_TOTAL  (A_NBIG + A_NSMALL)
#define B_NBX    (IN_DIM / BN)                   // 6
#define B_NBIG   (B_NBX * (M_ALL / BM))          // 1746
#define B_NSMALL (B_NBX * (M_CLS / BM) * ATOMS * ATOMS)  // 450
#define B_TOTAL  (B_NBIG + B_NSMALL)

// PHASE 0: d->h GELU, fp16 output (GEMM1 + GEMM3);  K = IN_DIM
// PHASE 1: h->d, fp32 output (GEMM2 scatter + GEMM4); K = HID
template<int PHASE>
__global__ __launch_bounds__(NTHREADS, 2)
void mlp_gemm(const __half* __restrict__ xh,
              const __half* __restrict__ wBig,
              const __half* __restrict__ wSmall,
              const __half* __restrict__ hm,
              const float* __restrict__ biasBig,
              const float* __restrict__ biasSmall,
              __half* __restrict__ outBigH,
              __half* __restrict__ outSmallH,
              float* __restrict__ outBigF,
              float* __restrict__ outE0,
              float* __restrict__ outSmallF)
{
    extern __shared__ char smem[];
    const uint32_t sb = smem_u32(smem);
    const int tid  = threadIdx.x;
    const int wid  = tid >> 5, lane = tid & 31;
    const int wm   = wid >> 1;               // 0..1  (M, 64 rows)
    const int wn   = wid & 1;                // 0..1  (N, 64 cols)

    const int bi = blockIdx.x;
    const int K  = (PHASE == 0) ? IN_DIM : HID;
    const int C  = K >> 6;
    int bm, bn, sub;
    const __half* A;
    const __half* B;
    const float* bias;
    if (PHASE == 0) {
        if (bi < A_NBIG) {
            sub = 0;
            bm = (bi / A_NBX) * BM; bn = (bi % A_NBX) * BN;
            A = xh; B = wBig; bias = biasBig;
        } else {
            int r = bi - A_NBIG;
            int a = r / (A_NBX * (M_CLS / BM));
            r -= a * (A_NBX * (M_CLS / BM));
            sub = 1 + a;
            bm = (r / A_NBX) * BM; bn = (r % A_NBX) * BN;
            A = xh + (size_t)M_PATCH * IN_DIM;
            B = wSmall + (size_t)a * HID * IN_DIM;
            bias = biasSmall + (size_t)a * HID;
        }
    } else {
        if (bi < B_NBIG) {
            sub = 0;
            bm = (bi / B_NBX) * BM; bn = (bi % B_NBX) * BN;
            A = xh; B = wBig; bias = biasBig;
        } else {
            int r = bi - B_NBIG;
            int z = r / (B_NBX * (M_CLS / BM));
            r -= z * (B_NBX * (M_CLS / BM));
            sub = 1 + z;
            bm = (r / B_NBX) * BM; bn = (r % B_NBX) * BN;
            int a = z / ATOMS, o = z % ATOMS;
            A = hm + (size_t)a * M_CLS * HID;
            B = wSmall + (size_t)o * IN_DIM * HID;
            bias = biasSmall + (size_t)o * IN_DIM;
        }
    }

    const __half* aG0 = A + (size_t)bm * K;
    const __half* bG0 = B + (size_t)bn * K;

    auto loadChunk = [&](int c) {
        const int slot = c % STAGES;
        const uint32_t aS = sb + (uint32_t)slot * (2 * STG_BYTES);
        const uint32_t bS = aS + STG_BYTES;
        const __half* aG = aG0 + c * BK;
        const __half* bG = bG0 + c * BK;
        #pragma unroll
        for (int t = 0; t < 8; t++) {
            int i = t * NTHREADS + tid;
            int row = i >> 3, g = i & 7;
            uint32_t off = (uint32_t)(row * 128 + g * 16);
            cp16(aS + sw128(off), aG + (size_t)row * K + g * 8);
        }
        #pragma unroll
        for (int t = 0; t < 8; t++) {
            int i = t * NTHREADS + tid;
            int row = i >> 3, g = i & 7;
            uint32_t off = (uint32_t)(row * 128 + g * 16);
            cp16(bS + sw128(off), bG + (size_t)row * K + g * 8);
        }
        CP_COMMIT();
    };

    float acc[4][8][4];
    #pragma unroll
    for (int i = 0; i < 4; i++)
        #pragma unroll
        for (int j = 0; j < 8; j++)
            #pragma unroll
            for (int q = 0; q < 4; q++) acc[i][j][q] = 0.0f;

    loadChunk(0);
    loadChunk(1);

    const int aRow = wm * 64 + (lane & 15);
    const int aCol = (lane >> 4) * 16;
    const int bRow = wn * 64 + ((lane >> 4) & 1) * 8 + (lane & 7);
    const int bCol = ((lane >> 3) & 1) * 16;

    for (int c = 0; c < C; c++) {
        if (c + 2 < C) { CP_WAIT(1); } else { CP_WAIT(0); }
        __syncthreads();
        if (c + 2 < C) loadChunk(c + 2);

        const int slot = c % STAGES;
        const uint32_t aS = sb + (uint32_t)slot * (2 * STG_BYTES);
        const uint32_t bS = aS + STG_BYTES;

        #pragma unroll
        for (int kk = 0; kk < 4; kk++) {
            uint32_t af[4][4];
            #pragma unroll
            for (int mt = 0; mt < 4; mt++) {
                uint32_t off = (uint32_t)((aRow + mt * 16) * 128 + kk * 32 + aCol);
                ldsm_x4(af[mt][0], af[mt][1], af[mt][2], af[mt][3], aS + sw128(off));
            }
            uint32_t bf[8][2];
            #pragma unroll
            for (int pr = 0; pr < 4; pr++) {
                uint32_t off = (uint32_t)((bRow + pr * 16) * 128 + kk * 32 + bCol);
                uint32_t r0, r1, r2, r3;
                ldsm_x4(r0, r1, r2, r3, bS + sw128(off));
                bf[pr * 2 + 0][0] = r0; bf[pr * 2 + 0][1] = r1;
                bf[pr * 2 + 1][0] = r2; bf[pr * 2 + 1][1] = r3;
            }
            #pragma unroll
            for (int mt = 0; mt < 4; mt++)
                #pragma unroll
                for (int nt = 0; nt < 8; nt++)
                    mma_f16(acc[mt][nt][0], acc[mt][nt][1], acc[mt][nt][2], acc[mt][nt][3],
                            af[mt][0], af[mt][1], af[mt][2], af[mt][3],
                            bf[nt][0], bf[nt][1]);
        }
    }

    // ---------------- epilogue ----------------
    const int q = lane & 3;
    #pragma unroll
    for (int mt = 0; mt < 4; mt++) {
        #pragma unroll
        for (int h = 0; h < 2; h++) {
            const int rowg = bm + wm * 64 + mt * 16 + (lane >> 2) + h * 8;
            __half* rpH = nullptr;
            float*  rpF = nullptr;
            if (PHASE == 0) {
                rpH = (sub == 0 ? outBigH : outSmallH + (size_t)(sub - 1) * M_CLS * HID)
                      + (size_t)rowg * HID;
            } else if (sub == 0) {
                if (rowg < M_PATCH) {
                    int bb = rowg / NUM_PATCH, p = rowg - bb * NUM_PATCH;
                    rpF = outBigF + (size_t)(bb * SEQ + NCLS + p) * IN_DIM;
                } else {
                    rpF = outE0 + (size_t)(rowg - M_PATCH) * IN_DIM;
                }
            } else {
                rpF = outSmallF + (size_t)(sub - 1) * M_CLS * IN_DIM + (size_t)rowg * IN_DIM;
            }
            #pragma unroll
            for (int nt = 0; nt < 8; nt++) {
                const int col = bn + wn * 64 + nt * 8 + q * 2;
                float v0 = acc[mt][nt][h * 2 + 0] + bias[col];
                float v1 = acc[mt][nt][h * 2 + 1] + bias[col + 1];
                if (PHASE == 0) {
                    v0 = gelu_f(v0); v1 = gelu_f(v1);
                    __half2 hh; hh.x = __float2half(v0); hh.y = __float2half(v1);
                    *reinterpret_cast<__half2*>(rpH + col) = hh;
                } else {
                    *reinterpret_cast<float2*>(rpF + col) = make_float2(v0, v1);
                }
            }
        }
    }
}

// ---------------- fused conversion kernel (single launch) ----------------
#define CX_BLK   (M_ALL * IN_DIM / 4 / 256)            // 27936
#define WT_W1    (IN_DIM / 32 * (HID / 32))            // 2304
#define WT_W2    (HID / 32 * (IN_DIM / 32))            // 2304
#define WT_WIN   (WT_W1 * ATOMS)
#define WT_WOUT  (WT_W2 * ATOMS)
#define CONV_TOTAL (CX_BLK + WT_W1 + WT_W2 + WT_WIN + WT_WOUT)

__global__ __launch_bounds__(256)
void conv_all(const float* __restrict__ x,   __half* __restrict__ xh,
              const float* __restrict__ W1,  __half* __restrict__ w1t,
              const float* __restrict__ W2,  __half* __restrict__ w2t,
              const float* __restrict__ Win, __half* __restrict__ wint,
              const float* __restrict__ Wout,__half* __restrict__ woutt)
{
    int bi = blockIdx.x;
    if (bi < CX_BLK) {
        int idx = bi * 256 + threadIdx.x;            // units of 4 elems
        int m  = idx / (IN_DIM / 4);
        int kp = (idx - m * (IN_DIM / 4)) * 4;
        int src;
        if (m < M_PATCH) { int b = m / NUM_PATCH, p = m - b * NUM_PATCH; src = b * SEQ + NCLS + p; }
        else             { int rr = m - M_PATCH; int b = rr / NCLS, t = rr - b * NCLS; src = b * SEQ + t; }
        float4 vv = *reinterpret_cast<const float4*>(x + (size_t)src * IN_DIM + kp);
        __half2 h01; h01.x = __float2half(vv.x); h01.y = __float2half(vv.y);
        __half2 h23; h23.x = __float2half(vv.z); h23.y = __float2half(vv.w);
        uint2 pk; pk.x = *reinterpret_cast<uint32_t*>(&h01); pk.y = *reinterpret_cast<uint32_t*>(&h23);
        *reinterpret_cast<uint2*>(xh + (size_t)m * IN_DIM + kp) = pk;
        return;
    }
    bi -= CX_BLK;

    const float* W; __half* Wt; int K, N, tileIdx;
    if (bi < WT_W1)                   { W = W1;  Wt = w1t;  K = IN_DIM; N = HID;    tileIdx = bi; }
    else if ((bi -= WT_W1)  < WT_W2)  { W = W2;  Wt = w2t;  K = HID;    N = IN_DIM; tileIdx = bi; }
    else if ((bi -= WT_W2)  < WT_WIN) {
        int z = bi / WT_W1; tileIdx = bi - z * WT_W1;
        W = Win  + (size_t)z * IN_DIM * HID; Wt = wint  + (size_t)z * HID * IN_DIM;
        K = IN_DIM; N = HID;
    } else {
        bi -= WT_WIN;
        int z = bi / WT_W2; tileIdx = bi - z * WT_W2;
        W = Wout + (size_t)z * HID * IN_DIM; Wt = woutt + (size_t)z * IN_DIM * HID;
        K = HID; N = IN_DIM;
    }

    __shared__ float t[32][33];
    const int ktiles = K / 32;
    int k0 = (tileIdx % ktiles) * 32, n0 = (tileIdx / ktiles) * 32;
    int tx = threadIdx.x & 31, ty = threadIdx.x >> 5;
    #pragma unroll
    for (int i = 0; i < 4; i++)
        t[ty + i * 8][tx] = W[(size_t)(k0 + ty + i * 8) * N + n0 + tx];
    __syncthreads();
    // vectorized half2 stores: 512 k-pair items = 32 n rows x 16 pairs
    #pragma unroll
    for (int it = 0; it < 2; it++) {
        int item = it * 256 + threadIdx.x;
        int n  = n0 + (item >> 4);
        int kp = (item & 15) * 2;
        __half2 hv;
        hv.x = __float2half(t[kp][item >> 4]);
        hv.y = __float2half(t[kp + 1][item >> 4]);
        *reinterpret_cast<__half2*>(Wt + (size_t)n * K + k0 + kp) = hv;
    }
}

// ---------------- gating + expert mixing ----------------
__global__ __launch_bounds__(256)
void gate_mix_kernel(const float* __restrict__ x,
                     const float* __restrict__ Wg,
                     const float* __restrict__ e0,
                     const float* __restrict__ allo,
                     float* __restrict__ out)
{
    const int n = blockIdx.x;
    const int b = n / NCLS;
    const int t = n - b * NCLS;
    const int a = t % ATOMS;

    __shared__ float scls[IN_DIM];
    __shared__ float slog[6];

    const float* crow = x + (size_t)(b * SEQ + t) * IN_DIM;
    for (int i = threadIdx.x; i < IN_DIM; i += 256) scls[i] = crow[i];
    __syncthreads();

    const int w = threadIdx.x >> 5, lane = threadIdx.x & 31;
    if (w < 6) {
        const float* wg = Wg + (size_t)t * IN_DIM * 6;
        float s = 0.0f;
        for (int d = lane; d < IN_DIM; d += 32)
            s = fmaf(scls[d], wg[(size_t)d * 6 + w], s);
        #pragma unroll
        for (int off = 16; off > 0; off >>= 1)
            s += __shfl_down_sync(0xffffffffu, s, off);
        if (lane == 0) slog[w] = s;
    }
    __syncthreads();

    float l[6];
    #pragma unroll
    for (int j = 0; j < 6; j++) l[j] = slog[j];
    int i0 = 0;
    #pragma unroll
    for (int j = 1; j < 6; j++) if (l[j] > l[i0]) i0 = j;
    int i1 = (i0 == 0) ? 1 : 0;
    #pragma unroll
    for (int j = 0; j < 6; j++) if (j != i0 && l[j] > l[i1]) i1 = j;
    float p1 = expf(l[i1] - l[i0]);
    float inv = 1.0f / (1.0f + p1);
    float w0 = inv, w1 = p1 * inv;

    const float* e0row = e0 + (size_t)n * IN_DIM;
    const float* r0 = (i0 == 0) ? e0row
        : allo + ((size_t)(a * ATOMS + (i0 - 1)) * M_CLS + n) * IN_DIM;
    const float* r1 = (i1 == 0) ? e0row
        : allo + ((size_t)(a * ATOMS + (i1 - 1)) * M_CLS + n) * IN_DIM;

    float* orow = out + (size_t)(b * SEQ + t) * IN_DIM;
    for (int c = threadIdx.x; c < IN_DIM; c += 256)
        orow[c] = w0 * r0[c] + w1 * r1[c];
}

// ---------------- launch ----------------
extern "C" void kernel_launch(void* const* d_in, const int* in_sizes, int n_in,
                              void* d_out, int out_size)
{
    const float* x     = (const float*)d_in[0];
    const float* W1    = (const float*)d_in[1];
    const float* b1    = (const float*)d_in[2];
    const float* W2    = (const float*)d_in[3];
    const float* b2    = (const float*)d_in[4];
    const float* W_in  = (const float*)d_in[5];
    const float* b_in  = (const float*)d_in[6];
    const float* W_out = (const float*)d_in[7];
    const float* b_out = (const float*)d_in[8];
    const float* Wg    = (const float*)d_in[9];
    float* out = (float*)d_out;

    static __half *xh = nullptr, *w1t, *hid, *w2t, *wint, *hm, *woutt;
    static float *allo, *e0;
    if (!xh) {
        cudaGetSymbolAddress((void**)&xh,    g_xh);
        cudaGetSymbolAddress((void**)&w1t,   g_w1t);
        cudaGetSymbolAddress((void**)&hid,   g_hid);
        cudaGetSymbolAddress((void**)&w2t,   g_w2t);
        cudaGetSymbolAddress((void**)&wint,  g_wint);
        cudaGetSymbolAddress((void**)&hm,    g_hm);
        cudaGetSymbolAddress((void**)&woutt, g_woutt);
        cudaGetSymbolAddress((void**)&allo,  g_allo);
        cudaGetSymbolAddress((void**)&e0,    g_e0);
        cudaFuncSetAttribute((const void*)mlp_gemm<0>,
                             cudaFuncAttributeMaxDynamicSharedMemorySize, SMEM_DYN);
        cudaFuncSetAttribute((const void*)mlp_gemm<1>,
                             cudaFuncAttributeMaxDynamicSharedMemorySize, SMEM_DYN);
    }

    // launch 1: all conversions fused
    conv_all<<<CONV_TOTAL, 256>>>(x, xh, W1, w1t, W2, w2t, W_in, wint, W_out, woutt);

    // launch 2: phase A (GEMM1 + GEMM3)
    mlp_gemm<0><<<A_TOTAL, NTHREADS, SMEM_DYN>>>(
        xh, w1t, wint, nullptr, b1, b_in,
        hid, hm, nullptr, nullptr, nullptr);

    // launch 3: phase B (GEMM2 + GEMM4)
    mlp_gemm<1><<<B_TOTAL, NTHREADS, SMEM_DYN>>>(
        hid, w2t, woutt, hm, b2, b_out,
        nullptr, nullptr, out, e0, allo);

    // launch 4: gating + mixing
    gate_mix_kernel<<<M_CLS, 256>>>(x, Wg, e0, allo, out);
}

// round 12
// speedup vs baseline: 1.0618x; 1.0457x over previous
#include <cuda_runtime.h>
#include <cuda_fp16.h>
#include <math.h>
#include <stdint.h>

// ---------------- problem constants ----------------
#define IN_DIM   768
#define HID      3072
#define BATCH    64
#define NCLS     6
#define NUM_PATCH 576
#define ATOMS    5
#define SEQ      (NCLS + NUM_PATCH)          // 582
#define M_PATCH  (BATCH * NUM_PATCH)         // 36864
#define M_CLS    (BATCH * NCLS)              // 384
#define M_ALL    (M_PATCH + M_CLS)           // 37248

// ---------------- device scratch ----------------
__device__ __half g_xh  [(size_t)M_ALL * IN_DIM];
__device__ __half g_w1t [(size_t)HID * IN_DIM];
__device__ __half g_hid [(size_t)M_ALL * HID];
__device__ __half g_w2t [(size_t)IN_DIM * HID];
__device__ __half g_wint [(size_t)ATOMS * HID * IN_DIM];
__device__ __half g_woutt[(size_t)ATOMS * IN_DIM * HID];
__device__ __half g_hm2 [(size_t)M_CLS * HID];            // per-token own-atom hidden
__device__ float g_e0  [(size_t)M_CLS * IN_DIM];
__device__ float g_moeOut[(size_t)M_CLS * 2 * IN_DIM];    // weighted expert rows
__device__ int   g_cnt [ATOMS];
__device__ int   g_lst [ATOMS * M_CLS];
__device__ float g_wls [ATOMS * M_CLS];
__device__ int2  g_gI  [M_CLS];
__device__ float2 g_gW [M_CLS];

__device__ __forceinline__ float gelu_f(float v) {
    return 0.5f * v * (1.0f + erff(v * 0.7071067811865476f));
}

// ---------------- PTX helpers (baseline sm_80+ only) ----------------
__device__ __forceinline__ uint32_t smem_u32(const void* p) {
    uint32_t a;
    asm("{ .reg .u64 t; cvta.to.shared.u64 t, %1; cvt.u32.u64 %0, t; }" : "=r"(a) : "l"(p));
    return a;
}
__device__ __forceinline__ void cp16(uint32_t d, const void* s) {
    asm volatile("cp.async.cg.shared.global [%0], [%1], 16;" :: "r"(d), "l"(s));
}
#define CP_COMMIT()  asm volatile("cp.async.commit_group;" ::: "memory")
#define CP_WAIT(n)   asm volatile("cp.async.wait_group %0;" :: "n"(n) : "memory")

__device__ __forceinline__ void ldsm_x4(uint32_t& r0, uint32_t& r1, uint32_t& r2, uint32_t& r3,
                                        uint32_t addr) {
    asm volatile("ldmatrix.sync.aligned.m8n8.x4.shared.b16 {%0,%1,%2,%3}, [%4];"
                 : "=r"(r0), "=r"(r1), "=r"(r2), "=r"(r3) : "r"(addr));
}
__device__ __forceinline__ void mma_f16(float& c0, float& c1, float& c2, float& c3,
                                        uint32_t a0, uint32_t a1, uint32_t a2, uint32_t a3,
                                        uint32_t b0, uint32_t b1) {
    asm volatile("mma.sync.aligned.m16n8k16.row.col.f32.f16.f16.f32 "
                 "{%0,%1,%2,%3}, {%4,%5,%6,%7}, {%8,%9}, {%0,%1,%2,%3};"
                 : "+f"(c0), "+f"(c1), "+f"(c2), "+f"(c3)
                 : "r"(a0), "r"(a1), "r"(a2), "r"(a3), "r"(b0), "r"(b1));
}
__device__ __forceinline__ uint32_t sw128(uint32_t off) {
    return off ^ ((off >> 3) & 0x70);
}

// ---------------- big HMMA GEMM (R9 core, big path only) ----------------
#define BM 128
#define BN 128
#define BK 64
#define STAGES 3
#define STG_BYTES (BM * 128)
#define SMEM_DYN (STAGES * 2 * STG_BYTES)        // 96 KB
#define NTHREADS 128

#define A_NBX    (HID / BN)                      // 24
#define A_NBIG   (A_NBX * (M_ALL / BM))          // 6984
#define B_NBX    (IN_DIM / BN)                   // 6
#define B_NBIG   (B_NBX * (M_ALL / BM))          // 1746

// PHASE 0: hid = gelu(xh @ w1t + b1), fp16 out;  K = IN_DIM
// PHASE 1: [out(patch); e0(cls)] = hid @ w2t + b2, fp32 scatter; K = HID
template<int PHASE>
__global__ __launch_bounds__(NTHREADS, 2)
void mlp_gemm(const __half* __restrict__ A,
              const __half* __restrict__ B,
              const float* __restrict__ bias,
              __half* __restrict__ outH,
              float* __restrict__ outF,
              float* __restrict__ outE0)
{
    extern __shared__ char smem[];
    const uint32_t sb = smem_u32(smem);
    const int tid  = threadIdx.x;
    const int wid  = tid >> 5, lane = tid & 31;
    const int wm   = wid >> 1;
    const int wn   = wid & 1;

    const int bi = blockIdx.x;
    const int K  = (PHASE == 0) ? IN_DIM : HID;
    const int C  = K >> 6;
    const int NBX = (PHASE == 0) ? A_NBX : B_NBX;
    const int bm = (bi / NBX) * BM;
    const int bn = (bi % NBX) * BN;

    const __half* aG0 = A + (size_t)bm * K;
    const __half* bG0 = B + (size_t)bn * K;

    auto loadChunk = [&](int c) {
        const int slot = c % STAGES;
        const uint32_t aS = sb + (uint32_t)slot * (2 * STG_BYTES);
        const uint32_t bS = aS + STG_BYTES;
        const __half* aG = aG0 + c * BK;
        const __half* bG = bG0 + c * BK;
        #pragma unroll
        for (int t = 0; t < 8; t++) {
            int i = t * NTHREADS + tid;
            int row = i >> 3, g = i & 7;
            uint32_t off = (uint32_t)(row * 128 + g * 16);
            cp16(aS + sw128(off), aG + (size_t)row * K + g * 8);
        }
        #pragma unroll
        for (int t = 0; t < 8; t++) {
            int i = t * NTHREADS + tid;
            int row = i >> 3, g = i & 7;
            uint32_t off = (uint32_t)(row * 128 + g * 16);
            cp16(bS + sw128(off), bG + (size_t)row * K + g * 8);
        }
        CP_COMMIT();
    };

    float acc[4][8][4];
    #pragma unroll
    for (int i = 0; i < 4; i++)
        #pragma unroll
        for (int j = 0; j < 8; j++)
            #pragma unroll
            for (int q = 0; q < 4; q++) acc[i][j][q] = 0.0f;

    loadChunk(0);
    loadChunk(1);

    const int aRow = wm * 64 + (lane & 15);
    const int aCol = (lane >> 4) * 16;
    const int bRow = wn * 64 + ((lane >> 4) & 1) * 8 + (lane & 7);
    const int bCol = ((lane >> 3) & 1) * 16;

    for (int c = 0; c < C; c++) {
        if (c + 2 < C) { CP_WAIT(1); } else { CP_WAIT(0); }
        __syncthreads();
        if (c + 2 < C) loadChunk(c + 2);

        const int slot = c % STAGES;
        const uint32_t aS = sb + (uint32_t)slot * (2 * STG_BYTES);
        const uint32_t bS = aS + STG_BYTES;

        #pragma unroll
        for (int kk = 0; kk < 4; kk++) {
            uint32_t af[4][4];
            #pragma unroll
            for (int mt = 0; mt < 4; mt++) {
                uint32_t off = (uint32_t)((aRow + mt * 16) * 128 + kk * 32 + aCol);
                ldsm_x4(af[mt][0], af[mt][1], af[mt][2], af[mt][3], aS + sw128(off));
            }
            uint32_t bf[8][2];
            #pragma unroll
            for (int pr = 0; pr < 4; pr++) {
                uint32_t off = (uint32_t)((bRow + pr * 16) * 128 + kk * 32 + bCol);
                uint32_t r0, r1, r2, r3;
                ldsm_x4(r0, r1, r2, r3, bS + sw128(off));
                bf[pr * 2 + 0][0] = r0; bf[pr * 2 + 0][1] = r1;
                bf[pr * 2 + 1][0] = r2; bf[pr * 2 + 1][1] = r3;
            }
            #pragma unroll
            for (int mt = 0; mt < 4; mt++)
                #pragma unroll
                for (int nt = 0; nt < 8; nt++)
                    mma_f16(acc[mt][nt][0], acc[mt][nt][1], acc[mt][nt][2], acc[mt][nt][3],
                            af[mt][0], af[mt][1], af[mt][2], af[mt][3],
                            bf[nt][0], bf[nt][1]);
        }
    }

    const int q = lane & 3;
    #pragma unroll
    for (int mt = 0; mt < 4; mt++) {
        #pragma unroll
        for (int h = 0; h < 2; h++) {
            const int rowg = bm + wm * 64 + mt * 16 + (lane >> 2) + h * 8;
            __half* rpH = nullptr;
            float*  rpF = nullptr;
            if (PHASE == 0) {
                rpH = outH + (size_t)rowg * HID;
            } else {
                if (rowg < M_PATCH) {
                    int bb = rowg / NUM_PATCH, p = rowg - bb * NUM_PATCH;
                    rpF = outF + (size_t)(bb * SEQ + NCLS + p) * IN_DIM;
                } else {
                    rpF = outE0 + (size_t)(rowg - M_PATCH) * IN_DIM;
                }
            }
            #pragma unroll
            for (int nt = 0; nt < 8; nt++) {
                const int col = bn + wn * 64 + nt * 8 + q * 2;
                float v0 = acc[mt][nt][h * 2 + 0] + bias[col];
                float v1 = acc[mt][nt][h * 2 + 1] + bias[col + 1];
                if (PHASE == 0) {
                    v0 = gelu_f(v0); v1 = gelu_f(v1);
                    __half2 hh; hh.x = __float2half(v0); hh.y = __float2half(v1);
                    *reinterpret_cast<__half2*>(rpH + col) = hh;
                } else {
                    *reinterpret_cast<float2*>(rpF + col) = make_float2(v0, v1);
                }
            }
        }
    }
}

// ---------------- gather GEMM: 64x128 tile, row-gathered A ----------------
// MODE 0: hm2[n] = gelu(xh[cls n] @ wint[a(n)] + b_in[a(n)])   K=768, N=3072
// MODE 1: moeOut[n,slot] = w * (hm2[n] @ woutt[o] + b_out[o])  K=3072, N=768
#define GBM 64
#define GBN 128
#define GSTG_A (GBM * 128)                 // 8 KB
#define GSTG_B (GBN * 128)                 // 16 KB
#define GSTG (GSTG_A + GSTG_B)             // 24 KB
#define GSMEM (1024 + 3 * GSTG)            // 74752
#define HM_BLOCKS  (6 * (HID / GBN))       // 144
#define MOE_BLOCKS (ATOMS * 6 * (IN_DIM / GBN))  // 180

template<int MODE>
__global__ __launch_bounds__(128, 2)
void gather_gemm(const __half* __restrict__ Abase,
                 const __half* __restrict__ Wt,
                 const float* __restrict__ bias,
                 __half* __restrict__ outH,
                 float* __restrict__ outF,
                 const int* __restrict__ cnt,
                 const int* __restrict__ lst,
                 const float* __restrict__ wls)
{
    extern __shared__ char smem[];
    const uint32_t sb = smem_u32(smem);
    const int tid = threadIdx.x;
    const int wid = tid >> 5, lane = tid & 31;
    const int wm = wid >> 1, wn = wid & 1;

    const int K = (MODE == 0) ? IN_DIM : HID;
    const int N = (MODE == 0) ? HID : IN_DIM;
    const int C = K >> 6;

    int zsel, mtile, ntile;
    if (MODE == 0) {
        const int nt = HID / GBN;                 // 24
        int mslot = blockIdx.x / nt; ntile = blockIdx.x % nt;
        zsel  = (mslot <= 1) ? 0 : (mslot - 1);   // atom
        mtile = (mslot <= 1) ? mslot : 0;
    } else {
        zsel  = blockIdx.x / 36;                  // expert o (0..4)
        int r = blockIdx.x % 36;
        mtile = r / 6; ntile = r % 6;
        if (mtile * GBM >= cnt[zsel]) return;
    }

    // setup row table: pointers + output index + weight
    if (tid < GBM) {
        const __half* rp; int oi; float w = 1.0f;
        if (MODE == 0) {
            int r = mtile * GBM + tid;
            int n = (zsel == 0) ? ((r < 64) ? r * 6 : (r - 64) * 6 + 5)
                                : r * 6 + zsel;
            rp = Abase + (size_t)(M_PATCH + n) * IN_DIM;
            oi = n;
        } else {
            int r = mtile * GBM + tid;
            if (r < cnt[zsel]) {
                int e = lst[zsel * M_CLS + r];
                int n = e & 0xFFFF, s = e >> 16;
                rp = Abase + (size_t)n * HID;
                oi = n * 2 + s;
                w  = wls[zsel * M_CLS + r];
            } else { rp = Abase; oi = -1; }
        }
        *reinterpret_cast<const __half**>(smem + tid * 8) = rp;
        reinterpret_cast<int*>(smem + 512)[tid]  = oi;
        reinterpret_cast<float*>(smem + 768)[tid] = w;
    }
    __syncthreads();

    const __half* bG0 = Wt + (size_t)zsel * N * K + (size_t)(ntile * GBN) * K;
    bias += (size_t)zsel * N;

    auto loadChunk = [&](int c) {
        const int slot = c % 3;
        const uint32_t aS = sb + 1024u + (uint32_t)slot * GSTG;
        const uint32_t bS = aS + GSTG_A;
        #pragma unroll
        for (int t = 0; t < 4; t++) {             // A: 512 chunks
            int i = t * 128 + tid;
            int row = i >> 3, g = i & 7;
            const __half* rp;
            asm("ld.shared.b64 %0, [%1];" : "=l"(rp) : "r"(sb + (uint32_t)(row * 8)));
            uint32_t off = (uint32_t)(row * 128 + g * 16);
            cp16(aS + sw128(off), rp + c * 64 + g * 8);
        }
        const __half* bG = bG0 + c * 64;
        #pragma unroll
        for (int t = 0; t < 8; t++) {             // B: 1024 chunks
            int i = t * 128 + tid;
            int row = i >> 3, g = i & 7;
            uint32_t off = (uint32_t)(row * 128 + g * 16);
            cp16(bS + sw128(off), bG + (size_t)row * K + g * 8);
        }
        CP_COMMIT();
    };

    float acc[2][8][4];
    #pragma unroll
    for (int i = 0; i < 2; i++)
        #pragma unroll
        for (int j = 0; j < 8; j++)
            #pragma unroll
            for (int q = 0; q < 4; q++) acc[i][j][q] = 0.0f;

    loadChunk(0);
    loadChunk(1);

    const int aRow = wm * 32 + (lane & 15);
    const int aCol = (lane >> 4) * 16;
    const int bRow = wn * 64 + ((lane >> 4) & 1) * 8 + (lane & 7);
    const int bCol = ((lane >> 3) & 1) * 16;

    for (int c = 0; c < C; c++) {
        if (c + 2 < C) { CP_WAIT(1); } else { CP_WAIT(0); }
        __syncthreads();
        if (c + 2 < C) loadChunk(c + 2);

        const int slot = c % 3;
        const uint32_t aS = sb + 1024u + (uint32_t)slot * GSTG;
        const uint32_t bS = aS + GSTG_A;

        #pragma unroll
        for (int kk = 0; kk < 4; kk++) {
            uint32_t af[2][4];
            #pragma unroll
            for (int mt = 0; mt < 2; mt++) {
                uint32_t off = (uint32_t)((aRow + mt * 16) * 128 + kk * 32 + aCol);
                ldsm_x4(af[mt][0], af[mt][1], af[mt][2], af[mt][3], aS + sw128(off));
            }
            uint32_t bf[8][2];
            #pragma unroll
            for (int pr = 0; pr < 4; pr++) {
                uint32_t off = (uint32_t)((bRow + pr * 16) * 128 + kk * 32 + bCol);
                uint32_t r0, r1, r2, r3;
                ldsm_x4(r0, r1, r2, r3, bS + sw128(off));
                bf[pr * 2 + 0][0] = r0; bf[pr * 2 + 0][1] = r1;
                bf[pr * 2 + 1][0] = r2; bf[pr * 2 + 1][1] = r3;
            }
            #pragma unroll
            for (int mt = 0; mt < 2; mt++)
                #pragma unroll
                for (int nt = 0; nt < 8; nt++)
                    mma_f16(acc[mt][nt][0], acc[mt][nt][1], acc[mt][nt][2], acc[mt][nt][3],
                            af[mt][0], af[mt][1], af[mt][2], af[mt][3],
                            bf[nt][0], bf[nt][1]);
        }
    }

    const int q = lane & 3;
    #pragma unroll
    for (int mt = 0; mt < 2; mt++) {
        #pragma unroll
        for (int h = 0; h < 2; h++) {
            const int rowg = wm * 32 + mt * 16 + (lane >> 2) + h * 8;
            int   oi = reinterpret_cast<int*>(smem + 512)[rowg];
            float w  = reinterpret_cast<float*>(smem + 768)[rowg];
            #pragma unroll
            for (int nt = 0; nt < 8; nt++) {
                const int col = ntile * GBN + wn * 64 + nt * 8 + q * 2;
                float v0 = acc[mt][nt][h * 2 + 0] + bias[col];
                float v1 = acc[mt][nt][h * 2 + 1] + bias[col + 1];
                if (MODE == 0) {
                    v0 = gelu_f(v0); v1 = gelu_f(v1);
                    __half2 hh; hh.x = __float2half(v0); hh.y = __float2half(v1);
                    *reinterpret_cast<__half2*>(outH + (size_t)oi * HID + col) = hh;
                } else if (oi >= 0) {
                    *reinterpret_cast<float2*>(outF + (size_t)oi * IN_DIM + col)
                        = make_float2(w * v0, w * v1);
                }
            }
        }
    }
}

// ---------------- fused conversion kernel ----------------
#define CX_BLK   (M_ALL * IN_DIM / 4 / 256)
#define WT_W1    (IN_DIM / 32 * (HID / 32))
#define WT_W2    (HID / 32 * (IN_DIM / 32))
#define WT_WIN   (WT_W1 * ATOMS)
#define WT_WOUT  (WT_W2 * ATOMS)
#define CONV_TOTAL (CX_BLK + WT_W1 + WT_W2 + WT_WIN + WT_WOUT)

__global__ __launch_bounds__(256)
void conv_all(const float* __restrict__ x,   __half* __restrict__ xh,
              const float* __restrict__ W1,  __half* __restrict__ w1t,
              const float* __restrict__ W2,  __half* __restrict__ w2t,
              const float* __restrict__ Win, __half* __restrict__ wint,
              const float* __restrict__ Wout,__half* __restrict__ woutt)
{
    int bi = blockIdx.x;
    if (bi < CX_BLK) {
        int idx = bi * 256 + threadIdx.x;
        int m  = idx / (IN_DIM / 4);
        int kp = (idx - m * (IN_DIM / 4)) * 4;
        int src;
        if (m < M_PATCH) { int b = m / NUM_PATCH, p = m - b * NUM_PATCH; src = b * SEQ + NCLS + p; }
        else             { int rr = m - M_PATCH; int b = rr / NCLS, t = rr - b * NCLS; src = b * SEQ + t; }
        float4 vv = *reinterpret_cast<const float4*>(x + (size_t)src * IN_DIM + kp);
        __half2 h01; h01.x = __float2half(vv.x); h01.y = __float2half(vv.y);
        __half2 h23; h23.x = __float2half(vv.z); h23.y = __float2half(vv.w);
        uint2 pk; pk.x = *reinterpret_cast<uint32_t*>(&h01); pk.y = *reinterpret_cast<uint32_t*>(&h23);
        *reinterpret_cast<uint2*>(xh + (size_t)m * IN_DIM + kp) = pk;
        return;
    }
    bi -= CX_BLK;

    const float* W; __half* Wt; int K, N, tileIdx;
    if (bi < WT_W1)                   { W = W1;  Wt = w1t;  K = IN_DIM; N = HID;    tileIdx = bi; }
    else if ((bi -= WT_W1)  < WT_W2)  { W = W2;  Wt = w2t;  K = HID;    N = IN_DIM; tileIdx = bi; }
    else if ((bi -= WT_W2)  < WT_WIN) {
        int z = bi / WT_W1; tileIdx = bi - z * WT_W1;
        W = Win  + (size_t)z * IN_DIM * HID; Wt = wint  + (size_t)z * HID * IN_DIM;
        K = IN_DIM; N = HID;
    } else {
        bi -= WT_WIN;
        int z = bi / WT_W2; tileIdx = bi - z * WT_W2;
        W = Wout + (size_t)z * HID * IN_DIM; Wt = woutt + (size_t)z * IN_DIM * HID;
        K = HID; N = IN_DIM;
    }

    __shared__ float t[32][33];
    const int ktiles = K / 32;
    int k0 = (tileIdx % ktiles) * 32, n0 = (tileIdx / ktiles) * 32;
    int tx = threadIdx.x & 31, ty = threadIdx.x >> 5;
    #pragma unroll
    for (int i = 0; i < 4; i++)
        t[ty + i * 8][tx] = W[(size_t)(k0 + ty + i * 8) * N + n0 + tx];
    __syncthreads();
    #pragma unroll
    for (int it = 0; it < 2; it++) {
        int item = it * 256 + threadIdx.x;
        int n  = n0 + (item >> 4);
        int kp = (item & 15) * 2;
        __half2 hv;
        hv.x = __float2half(t[kp][item >> 4]);
        hv.y = __float2half(t[kp + 1][item >> 4]);
        *reinterpret_cast<__half2*>(Wt + (size_t)n * K + k0 + kp) = hv;
    }
}

// ---------------- gating: logits, top-2, expert lists ----------------
__global__ __launch_bounds__(192)
void gate_sel(const float* __restrict__ x,
              const float* __restrict__ Wg,
              int* __restrict__ cnt, int* __restrict__ lst, float* __restrict__ wls,
              int2* __restrict__ gI, float2* __restrict__ gW)
{
    const int n = blockIdx.x;
    const int b = n / NCLS;
    const int t = n - b * NCLS;

    __shared__ float scls[IN_DIM];
    __shared__ float slog[6];

    const float* crow = x + (size_t)(b * SEQ + t) * IN_DIM;
    for (int i = threadIdx.x; i < IN_DIM; i += 192) scls[i] = crow[i];
    __syncthreads();

    const int w = threadIdx.x >> 5, lane = threadIdx.x & 31;
    {
        const float* wg = Wg + (size_t)t * IN_DIM * 6;
        float s = 0.0f;
        for (int d = lane; d < IN_DIM; d += 32)
            s = fmaf(scls[d], wg[(size_t)d * 6 + w], s);
        #pragma unroll
        for (int off = 16; off > 0; off >>= 1)
            s += __shfl_down_sync(0xffffffffu, s, off);
        if (lane == 0) slog[w] = s;
    }
    __syncthreads();

    if (threadIdx.x == 0) {
        float l[6];
        #pragma unroll
        for (int j = 0; j < 6; j++) l[j] = slog[j];
        int i0 = 0;
        #pragma unroll
        for (int j = 1; j < 6; j++) if (l[j] > l[i0]) i0 = j;
        int i1 = (i0 == 0) ? 1 : 0;
        #pragma unroll
        for (int j = 0; j < 6; j++) if (j != i0 && l[j] > l[i1]) i1 = j;
        float p1 = expf(l[i1] - l[i0]);
        float inv = 1.0f / (1.0f + p1);
        float w0 = inv, w1 = p1 * inv;
        gI[n] = make_int2(i0, i1);
        gW[n] = make_float2(w0, w1);
        if (i0 > 0) {
            int idx = atomicAdd(&cnt[i0 - 1], 1);
            lst[(i0 - 1) * M_CLS + idx] = n;              // slot 0
            wls[(i0 - 1) * M_CLS + idx] = w0;
        }
        if (i1 > 0) {
            int idx = atomicAdd(&cnt[i1 - 1], 1);
            lst[(i1 - 1) * M_CLS + idx] = n | (1 << 16);  // slot 1
            wls[(i1 - 1) * M_CLS + idx] = w1;
        }
    }
}

// ---------------- final mix ----------------
__global__ __launch_bounds__(192)
void final_mix(const float* __restrict__ e0,
               const float* __restrict__ moeOut,
               const int2* __restrict__ gI,
               const float2* __restrict__ gW,
               float* __restrict__ out)
{
    const int n = blockIdx.x;
    const int b = n / NCLS;
    const int t = n - b * NCLS;
    int2  ii = gI[n];
    float2 ww = gW[n];
    const float* e0row = e0 + (size_t)n * IN_DIM;
    const float* m0 = moeOut + (size_t)(n * 2 + 0) * IN_DIM;
    const float* m1 = moeOut + (size_t)(n * 2 + 1) * IN_DIM;
    float* orow = out + (size_t)(b * SEQ + t) * IN_DIM;
    for (int c = threadIdx.x; c < IN_DIM; c += 192) {
        float v = (ii.x == 0) ? ww.x * e0row[c] : m0[c];
        v      += (ii.y == 0) ? ww.y * e0row[c] : m1[c];
        orow[c] = v;
    }
}

// ---------------- launch ----------------
extern "C" void kernel_launch(void* const* d_in, const int* in_sizes, int n_in,
                              void* d_out, int out_size)
{
    const float* x     = (const float*)d_in[0];
    const float* W1    = (const float*)d_in[1];
    const float* b1    = (const float*)d_in[2];
    const float* W2    = (const float*)d_in[3];
    const float* b2    = (const float*)d_in[4];
    const float* W_in  = (const float*)d_in[5];
    const float* b_in  = (const float*)d_in[6];
    const float* W_out = (const float*)d_in[7];
    const float* b_out = (const float*)d_in[8];
    const float* Wg    = (const float*)d_in[9];
    float* out = (float*)d_out;

    static __half *xh = nullptr, *w1t, *hid, *w2t, *wint, *woutt, *hm2;
    static float *e0, *moeOut, *wls;
    static int *cnt, *lst;
    static int2 *gI;
    static float2 *gW;
    if (!xh) {
        cudaGetSymbolAddress((void**)&xh,    g_xh);
        cudaGetSymbolAddress((void**)&w1t,   g_w1t);
        cudaGetSymbolAddress((void**)&hid,   g_hid);
        cudaGetSymbolAddress((void**)&w2t,   g_w2t);
        cudaGetSymbolAddress((void**)&wint,  g_wint);
        cudaGetSymbolAddress((void**)&woutt, g_woutt);
        cudaGetSymbolAddress((void**)&hm2,   g_hm2);
        cudaGetSymbolAddress((void**)&e0,    g_e0);
        cudaGetSymbolAddress((void**)&moeOut,g_moeOut);
        cudaGetSymbolAddress((void**)&cnt,   g_cnt);
        cudaGetSymbolAddress((void**)&lst,   g_lst);
        cudaGetSymbolAddress((void**)&wls,   g_wls);
        cudaGetSymbolAddress((void**)&gI,    g_gI);
        cudaGetSymbolAddress((void**)&gW,    g_gW);
        cudaFuncSetAttribute((const void*)mlp_gemm<0>,
                             cudaFuncAttributeMaxDynamicSharedMemorySize, SMEM_DYN);
        cudaFuncSetAttribute((const void*)mlp_gemm<1>,
                             cudaFuncAttributeMaxDynamicSharedMemorySize, SMEM_DYN);
        cudaFuncSetAttribute((const void*)gather_gemm<0>,
                             cudaFuncAttributeMaxDynamicSharedMemorySize, GSMEM);
        cudaFuncSetAttribute((const void*)gather_gemm<1>,
                             cudaFuncAttributeMaxDynamicSharedMemorySize, GSMEM);
    }

    // 0: reset expert counters (async memset node, capture-safe)
    cudaMemsetAsync(cnt, 0, ATOMS * sizeof(int));

    // 1: conversions
    conv_all<<<CONV_TOTAL, 256>>>(x, xh, W1, w1t, W2, w2t, W_in, wint, W_out, woutt);

    // 2: gating (x, Wg only)
    gate_sel<<<M_CLS, 192>>>(x, Wg, cnt, lst, wls, gI, gW);

    // 3: per-token own-atom hidden (hm2)
    gather_gemm<0><<<HM_BLOCKS, 128, GSMEM>>>(
        xh, wint, b_in, hm2, nullptr, nullptr, nullptr, nullptr);

    // 4: selected expert rows -> weighted moeOut
    gather_gemm<1><<<MOE_BLOCKS, 128, GSMEM>>>(
        hm2, woutt, b_out, nullptr, moeOut, cnt, lst, wls);

    // 5: phase A big GEMM
    mlp_gemm<0><<<A_NBIG, NTHREADS, SMEM_DYN>>>(xh, w1t, b1, hid, nullptr, nullptr);

    // 6: phase B big GEMM (patch -> out, cls -> e0)
    mlp_gemm<1><<<B_NBIG, NTHREADS, SMEM_DYN>>>(hid, w2t, b2, nullptr, out, e0);

    // 7: final mix of cls rows
    final_mix<<<M_CLS, 192>>>(e0, moeOut, gI, gW, out);
}

// round 13
// speedup vs baseline: 1.1629x; 1.0952x over previous
#include <cuda_runtime.h>
#include <cuda_fp16.h>
#include <math.h>
#include <stdint.h>

// ---------------- problem constants ----------------
#define IN_DIM   768
#define HID      3072
#define BATCH    64
#define NCLS     6
#define NUM_PATCH 576
#define ATOMS    5
#define SEQ      (NCLS + NUM_PATCH)          // 582
#define M_PATCH  (BATCH * NUM_PATCH)         // 36864
#define M_CLS    (BATCH * NCLS)              // 384
#define M_ALL    (M_PATCH + M_CLS)           // 37248

// ---------------- device scratch ----------------
__device__ __half g_xh  [(size_t)M_ALL * IN_DIM];
__device__ __half g_w1t [(size_t)HID * IN_DIM];
__device__ __half g_hid [(size_t)M_ALL * HID];
__device__ __half g_w2t [(size_t)IN_DIM * HID];
__device__ __half g_wint [(size_t)ATOMS * HID * IN_DIM];
__device__ __half g_woutt[(size_t)ATOMS * IN_DIM * HID];
__device__ __half g_hm2 [(size_t)M_CLS * HID];
__device__ float g_e0  [(size_t)M_CLS * IN_DIM];
__device__ float g_moeOut[(size_t)M_CLS * 2 * IN_DIM];
__device__ int   g_cnt [ATOMS];
__device__ int   g_lst [ATOMS * M_CLS];
__device__ float g_wls [ATOMS * M_CLS];
__device__ int2  g_gI  [M_CLS];
__device__ float2 g_gW [M_CLS];

__device__ __forceinline__ float gelu_f(float v) {
    return 0.5f * v * (1.0f + erff(v * 0.7071067811865476f));
}

// ---------------- PTX helpers ----------------
__device__ __forceinline__ uint32_t smem_u32(const void* p) {
    uint32_t a;
    asm("{ .reg .u64 t; cvta.to.shared.u64 t, %1; cvt.u32.u64 %0, t; }" : "=r"(a) : "l"(p));
    return a;
}
__device__ __forceinline__ void cp16(uint32_t d, const void* s) {
    asm volatile("cp.async.cg.shared.global [%0], [%1], 16;" :: "r"(d), "l"(s));
}
#define CP_COMMIT()  asm volatile("cp.async.commit_group;" ::: "memory")
#define CP_WAIT(n)   asm volatile("cp.async.wait_group %0;" :: "n"(n) : "memory")

__device__ __forceinline__ void ldsm_x4(uint32_t& r0, uint32_t& r1, uint32_t& r2, uint32_t& r3,
                                        uint32_t addr) {
    asm volatile("ldmatrix.sync.aligned.m8n8.x4.shared.b16 {%0,%1,%2,%3}, [%4];"
                 : "=r"(r0), "=r"(r1), "=r"(r2), "=r"(r3) : "r"(addr));
}
__device__ __forceinline__ void mma_f16(float& c0, float& c1, float& c2, float& c3,
                                        uint32_t a0, uint32_t a1, uint32_t a2, uint32_t a3,
                                        uint32_t b0, uint32_t b1) {
    asm volatile("mma.sync.aligned.m16n8k16.row.col.f32.f16.f16.f32 "
                 "{%0,%1,%2,%3}, {%4,%5,%6,%7}, {%8,%9}, {%0,%1,%2,%3};"
                 : "+f"(c0), "+f"(c1), "+f"(c2), "+f"(c3)
                 : "r"(a0), "r"(a1), "r"(a2), "r"(a3), "r"(b0), "r"(b1));
}
__device__ __forceinline__ uint32_t sw128(uint32_t off) {
    return off ^ ((off >> 3) & 0x70);
}

// ---------------- fused GEMM (big path + gathered MoE path in one grid) ----------------
#define BM 128
#define BN 128
#define BK 64
#define STAGES 3
#define STG_BYTES (BM * 128)
#define SMEM_DYN (STAGES * 2 * STG_BYTES)        // 96 KB (covers both paths)
#define NTHREADS 128

#define A_NBX    (HID / BN)                      // 24
#define A_NBIG   (A_NBX * (M_ALL / BM))          // 6984
#define B_NBX    (IN_DIM / BN)                   // 6
#define B_NBIG   (B_NBX * (M_ALL / BM))          // 1746

#define GBM 64
#define GBN 128
#define GSTG_A (GBM * 128)                       // 8 KB
#define GSTG_B (GBN * 128)                       // 16 KB
#define GSTG (GSTG_A + GSTG_B)                   // 24 KB
#define HM_BLOCKS  (6 * (HID / GBN))             // 144
#define MOE_BLOCKS (ATOMS * 6 * (IN_DIM / GBN))  // 180
#define A_TOTAL (A_NBIG + HM_BLOCKS)             // 7128
#define B_TOTAL (B_NBIG + MOE_BLOCKS)            // 1926

// PHASE 0: big = [hid = gelu(xh@w1t+b1)] ; gather = [hm2 = gelu(cls@wint[a]+b_in)]
// PHASE 1: big = [out/e0 = hid@w2t+b2]   ; gather = [moeOut = w*(hm2@woutt[o]+b_out)]
template<int PHASE>
__global__ __launch_bounds__(NTHREADS, 2)
void fused_gemm(const __half* __restrict__ A,       // xh / hid
                const __half* __restrict__ Bw,      // w1t / w2t
                const float* __restrict__ bias,     // b1 / b2
                __half* __restrict__ outH,          // hid / -
                float* __restrict__ outF,           // - / out
                float* __restrict__ outE0,          // - / e0
                const __half* __restrict__ Ag,      // xh / hm2
                const __half* __restrict__ Wsm,     // wint / woutt
                const float* __restrict__ biasSm,   // b_in / b_out
                __half* __restrict__ outGH,         // hm2 / -
                float* __restrict__ outGF,          // - / moeOut
                const int* __restrict__ cnt,
                const int* __restrict__ lst,
                const float* __restrict__ wls)
{
    extern __shared__ char smem[];
    const uint32_t sb = smem_u32(smem);
    const int tid  = threadIdx.x;
    const int wid  = tid >> 5, lane = tid & 31;
    const int NBIG = (PHASE == 0) ? A_NBIG : B_NBIG;
    const int K    = (PHASE == 0) ? IN_DIM : HID;
    const int C    = K >> 6;

    if (blockIdx.x < (unsigned)NBIG) {
        // ================= BIG PATH: 128x128 tile, 4 warps 2x2, warp tile 64x64 =================
        const int wm = wid >> 1, wn = wid & 1;
        const int bi = blockIdx.x;
        const int NBX = (PHASE == 0) ? A_NBX : B_NBX;
        const int bm = (bi / NBX) * BM;
        const int bn = (bi % NBX) * BN;

        const __half* aG0 = A + (size_t)bm * K;
        const __half* bG0 = Bw + (size_t)bn * K;

        auto loadChunk = [&](int c) {
            const int slot = c % STAGES;
            const uint32_t aS = sb + (uint32_t)slot * (2 * STG_BYTES);
            const uint32_t bS = aS + STG_BYTES;
            const __half* aG = aG0 + c * BK;
            const __half* bG = bG0 + c * BK;
            #pragma unroll
            for (int t = 0; t < 8; t++) {
                int i = t * NTHREADS + tid;
                int row = i >> 3, g = i & 7;
                uint32_t off = (uint32_t)(row * 128 + g * 16);
                cp16(aS + sw128(off), aG + (size_t)row * K + g * 8);
            }
            #pragma unroll
            for (int t = 0; t < 8; t++) {
                int i = t * NTHREADS + tid;
                int row = i >> 3, g = i & 7;
                uint32_t off = (uint32_t)(row * 128 + g * 16);
                cp16(bS + sw128(off), bG + (size_t)row * K + g * 8);
            }
            CP_COMMIT();
        };

        float acc[4][8][4];
        #pragma unroll
        for (int i = 0; i < 4; i++)
            #pragma unroll
            for (int j = 0; j < 8; j++)
                #pragma unroll
                for (int q = 0; q < 4; q++) acc[i][j][q] = 0.0f;

        loadChunk(0);
        loadChunk(1);

        const int aRow = wm * 64 + (lane & 15);
        const int aCol = (lane >> 4) * 16;
        const int bRow = wn * 64 + ((lane >> 4) & 1) * 8 + (lane & 7);
        const int bCol = ((lane >> 3) & 1) * 16;

        for (int c = 0; c < C; c++) {
            if (c + 2 < C) { CP_WAIT(1); } else { CP_WAIT(0); }
            __syncthreads();
            if (c + 2 < C) loadChunk(c + 2);

            const int slot = c % STAGES;
            const uint32_t aS = sb + (uint32_t)slot * (2 * STG_BYTES);
            const uint32_t bS = aS + STG_BYTES;

            #pragma unroll
            for (int kk = 0; kk < 4; kk++) {
                uint32_t af[4][4];
                #pragma unroll
                for (int mt = 0; mt < 4; mt++) {
                    uint32_t off = (uint32_t)((aRow + mt * 16) * 128 + kk * 32 + aCol);
                    ldsm_x4(af[mt][0], af[mt][1], af[mt][2], af[mt][3], aS + sw128(off));
                }
                uint32_t bf[8][2];
                #pragma unroll
                for (int pr = 0; pr < 4; pr++) {
                    uint32_t off = (uint32_t)((bRow + pr * 16) * 128 + kk * 32 + bCol);
                    uint32_t r0, r1, r2, r3;
                    ldsm_x4(r0, r1, r2, r3, bS + sw128(off));
                    bf[pr * 2 + 0][0] = r0; bf[pr * 2 + 0][1] = r1;
                    bf[pr * 2 + 1][0] = r2; bf[pr * 2 + 1][1] = r3;
                }
                #pragma unroll
                for (int mt = 0; mt < 4; mt++)
                    #pragma unroll
                    for (int nt = 0; nt < 8; nt++)
                        mma_f16(acc[mt][nt][0], acc[mt][nt][1], acc[mt][nt][2], acc[mt][nt][3],
                                af[mt][0], af[mt][1], af[mt][2], af[mt][3],
                                bf[nt][0], bf[nt][1]);
            }
        }

        const int q = lane & 3;
        #pragma unroll
        for (int mt = 0; mt < 4; mt++) {
            #pragma unroll
            for (int h = 0; h < 2; h++) {
                const int rowg = bm + wm * 64 + mt * 16 + (lane >> 2) + h * 8;
                __half* rpH = nullptr;
                float*  rpF = nullptr;
                if (PHASE == 0) {
                    rpH = outH + (size_t)rowg * HID;
                } else {
                    if (rowg < M_PATCH) {
                        int bb = rowg / NUM_PATCH, p = rowg - bb * NUM_PATCH;
                        rpF = outF + (size_t)(bb * SEQ + NCLS + p) * IN_DIM;
                    } else {
                        rpF = outE0 + (size_t)(rowg - M_PATCH) * IN_DIM;
                    }
                }
                #pragma unroll
                for (int nt = 0; nt < 8; nt++) {
                    const int col = bn + wn * 64 + nt * 8 + q * 2;
                    float v0 = acc[mt][nt][h * 2 + 0] + bias[col];
                    float v1 = acc[mt][nt][h * 2 + 1] + bias[col + 1];
                    if (PHASE == 0) {
                        v0 = gelu_f(v0); v1 = gelu_f(v1);
                        __half2 hh; hh.x = __float2half(v0); hh.y = __float2half(v1);
                        *reinterpret_cast<__half2*>(rpH + col) = hh;
                    } else {
                        *reinterpret_cast<float2*>(rpF + col) = make_float2(v0, v1);
                    }
                }
            }
        }
    } else {
        // ================= GATHER PATH: 64x128 tile, 4 warps 2x2, warp tile 32x64 =================
        const int gbi = blockIdx.x - NBIG;
        const int wm = wid >> 1, wn = wid & 1;
        const int N = (PHASE == 0) ? HID : IN_DIM;

        int zsel, mtile, ntile;
        if (PHASE == 0) {
            const int nt = HID / GBN;                 // 24
            int mslot = gbi / nt; ntile = gbi % nt;
            zsel  = (mslot <= 1) ? 0 : (mslot - 1);
            mtile = (mslot <= 1) ? mslot : 0;
        } else {
            zsel  = gbi / 36;
            int r = gbi % 36;
            mtile = r / 6; ntile = r % 6;
            if (mtile * GBM >= cnt[zsel]) return;
        }

        if (tid < GBM) {
            const __half* rp; int oi; float w = 1.0f;
            if (PHASE == 0) {
                int r = mtile * GBM + tid;
                int n = (zsel == 0) ? ((r < 64) ? r * 6 : (r - 64) * 6 + 5)
                                    : r * 6 + zsel;
                rp = Ag + (size_t)(M_PATCH + n) * IN_DIM;
                oi = n;
            } else {
                int r = mtile * GBM + tid;
                if (r < cnt[zsel]) {
                    int e = lst[zsel * M_CLS + r];
                    int n = e & 0xFFFF, s = e >> 16;
                    rp = Ag + (size_t)n * HID;
                    oi = n * 2 + s;
                    w  = wls[zsel * M_CLS + r];
                } else { rp = Ag; oi = -1; }
            }
            *reinterpret_cast<const __half**>(smem + tid * 8) = rp;
            reinterpret_cast<int*>(smem + 512)[tid]  = oi;
            reinterpret_cast<float*>(smem + 768)[tid] = w;
        }
        __syncthreads();

        const __half* bG0 = Wsm + (size_t)zsel * N * K + (size_t)(ntile * GBN) * K;
        const float* biasZ = biasSm + (size_t)zsel * N;

        auto loadChunkG = [&](int c) {
            const int slot = c % 3;
            const uint32_t aS = sb + 1024u + (uint32_t)slot * GSTG;
            const uint32_t bS = aS + GSTG_A;
            #pragma unroll
            for (int t = 0; t < 4; t++) {
                int i = t * 128 + tid;
                int row = i >> 3, g = i & 7;
                const __half* rp;
                asm("ld.shared.b64 %0, [%1];" : "=l"(rp) : "r"(sb + (uint32_t)(row * 8)));
                uint32_t off = (uint32_t)(row * 128 + g * 16);
                cp16(aS + sw128(off), rp + c * 64 + g * 8);
            }
            const __half* bG = bG0 + c * 64;
            #pragma unroll
            for (int t = 0; t < 8; t++) {
                int i = t * 128 + tid;
                int row = i >> 3, g = i & 7;
                uint32_t off = (uint32_t)(row * 128 + g * 16);
                cp16(bS + sw128(off), bG + (size_t)row * K + g * 8);
            }
            CP_COMMIT();
        };

        float acc[2][8][4];
        #pragma unroll
        for (int i = 0; i < 2; i++)
            #pragma unroll
            for (int j = 0; j < 8; j++)
                #pragma unroll
                for (int q = 0; q < 4; q++) acc[i][j][q] = 0.0f;

        loadChunkG(0);
        loadChunkG(1);

        const int aRow = wm * 32 + (lane & 15);
        const int aCol = (lane >> 4) * 16;
        const int bRow = wn * 64 + ((lane >> 4) & 1) * 8 + (lane & 7);
        const int bCol = ((lane >> 3) & 1) * 16;

        for (int c = 0; c < C; c++) {
            if (c + 2 < C) { CP_WAIT(1); } else { CP_WAIT(0); }
            __syncthreads();
            if (c + 2 < C) loadChunkG(c + 2);

            const int slot = c % 3;
            const uint32_t aS = sb + 1024u + (uint32_t)slot * GSTG;
            const uint32_t bS = aS + GSTG_A;

            #pragma unroll
            for (int kk = 0; kk < 4; kk++) {
                uint32_t af[2][4];
                #pragma unroll
                for (int mt = 0; mt < 2; mt++) {
                    uint32_t off = (uint32_t)((aRow + mt * 16) * 128 + kk * 32 + aCol);
                    ldsm_x4(af[mt][0], af[mt][1], af[mt][2], af[mt][3], aS + sw128(off));
                }
                uint32_t bf[8][2];
                #pragma unroll
                for (int pr = 0; pr < 4; pr++) {
                    uint32_t off = (uint32_t)((bRow + pr * 16) * 128 + kk * 32 + bCol);
                    uint32_t r0, r1, r2, r3;
                    ldsm_x4(r0, r1, r2, r3, bS + sw128(off));
                    bf[pr * 2 + 0][0] = r0; bf[pr * 2 + 0][1] = r1;
                    bf[pr * 2 + 1][0] = r2; bf[pr * 2 + 1][1] = r3;
                }
                #pragma unroll
                for (int mt = 0; mt < 2; mt++)
                    #pragma unroll
                    for (int nt = 0; nt < 8; nt++)
                        mma_f16(acc[mt][nt][0], acc[mt][nt][1], acc[mt][nt][2], acc[mt][nt][3],
                                af[mt][0], af[mt][1], af[mt][2], af[mt][3],
                                bf[nt][0], bf[nt][1]);
            }
        }

        const int q = lane & 3;
        #pragma unroll
        for (int mt = 0; mt < 2; mt++) {
            #pragma unroll
            for (int h = 0; h < 2; h++) {
                const int rowg = wm * 32 + mt * 16 + (lane >> 2) + h * 8;
                int   oi = reinterpret_cast<int*>(smem + 512)[rowg];
                float w  = reinterpret_cast<float*>(smem + 768)[rowg];
                #pragma unroll
                for (int nt = 0; nt < 8; nt++) {
                    const int col = ntile * GBN + wn * 64 + nt * 8 + q * 2;
                    float v0 = acc[mt][nt][h * 2 + 0] + biasZ[col];
                    float v1 = acc[mt][nt][h * 2 + 1] + biasZ[col + 1];
                    if (PHASE == 0) {
                        v0 = gelu_f(v0); v1 = gelu_f(v1);
                        __half2 hh; hh.x = __float2half(v0); hh.y = __float2half(v1);
                        *reinterpret_cast<__half2*>(outGH + (size_t)oi * HID + col) = hh;
                    } else if (oi >= 0) {
                        *reinterpret_cast<float2*>(outGF + (size_t)oi * IN_DIM + col)
                            = make_float2(w * v0, w * v1);
                    }
                }
            }
        }
    }
}

// ---------------- fused conversion + gating kernel ----------------
#define CX_BLK   (M_ALL * IN_DIM / 4 / 256)
#define WT_W1    (IN_DIM / 32 * (HID / 32))
#define WT_W2    (HID / 32 * (IN_DIM / 32))
#define WT_WIN   (WT_W1 * ATOMS)
#define WT_WOUT  (WT_W2 * ATOMS)
#define CONV_BLOCKS (CX_BLK + WT_W1 + WT_W2 + WT_WIN + WT_WOUT)
#define CONV_TOTAL (CONV_BLOCKS + M_CLS)

__global__ __launch_bounds__(256)
void conv_all(const float* __restrict__ x,   __half* __restrict__ xh,
              const float* __restrict__ W1,  __half* __restrict__ w1t,
              const float* __restrict__ W2,  __half* __restrict__ w2t,
              const float* __restrict__ Win, __half* __restrict__ wint,
              const float* __restrict__ Wout,__half* __restrict__ woutt,
              const float* __restrict__ Wg,
              int* __restrict__ cnt, int* __restrict__ lst, float* __restrict__ wls,
              int2* __restrict__ gI, float2* __restrict__ gW)
{
    int bi = blockIdx.x;
    if (bi < CX_BLK) {
        int idx = bi * 256 + threadIdx.x;
        int m  = idx / (IN_DIM / 4);
        int kp = (idx - m * (IN_DIM / 4)) * 4;
        int src;
        if (m < M_PATCH) { int b = m / NUM_PATCH, p = m - b * NUM_PATCH; src = b * SEQ + NCLS + p; }
        else             { int rr = m - M_PATCH; int b = rr / NCLS, t = rr - b * NCLS; src = b * SEQ + t; }
        float4 vv = *reinterpret_cast<const float4*>(x + (size_t)src * IN_DIM + kp);
        __half2 h01; h01.x = __float2half(vv.x); h01.y = __float2half(vv.y);
        __half2 h23; h23.x = __float2half(vv.z); h23.y = __float2half(vv.w);
        uint2 pk; pk.x = *reinterpret_cast<uint32_t*>(&h01); pk.y = *reinterpret_cast<uint32_t*>(&h23);
        *reinterpret_cast<uint2*>(xh + (size_t)m * IN_DIM + kp) = pk;
        return;
    }
    bi -= CX_BLK;

    if (bi >= WT_W1 + WT_W2 + WT_WIN + WT_WOUT) {
        // ---- gating block: one per cls token ----
        const int n = bi - (WT_W1 + WT_W2 + WT_WIN + WT_WOUT);
        const int b = n / NCLS;
        const int t = n - b * NCLS;

        __shared__ float scls[IN_DIM];
        __shared__ float slog[6];

        const float* crow = x + (size_t)(b * SEQ + t) * IN_DIM;
        for (int i = threadIdx.x; i < IN_DIM; i += 256) scls[i] = crow[i];
        __syncthreads();

        const int w = threadIdx.x >> 5, lane = threadIdx.x & 31;
        if (w < 6) {
            const float* wg = Wg + (size_t)t * IN_DIM * 6;
            float s = 0.0f;
            for (int d = lane; d < IN_DIM; d += 32)
                s = fmaf(scls[d], wg[(size_t)d * 6 + w], s);
            #pragma unroll
            for (int off = 16; off > 0; off >>= 1)
                s += __shfl_down_sync(0xffffffffu, s, off);
            if (lane == 0) slog[w] = s;
        }
        __syncthreads();

        if (threadIdx.x == 0) {
            float l[6];
            #pragma unroll
            for (int j = 0; j < 6; j++) l[j] = slog[j];
            int i0 = 0;
            #pragma unroll
            for (int j = 1; j < 6; j++) if (l[j] > l[i0]) i0 = j;
            int i1 = (i0 == 0) ? 1 : 0;
            #pragma unroll
            for (int j = 0; j < 6; j++) if (j != i0 && l[j] > l[i1]) i1 = j;
            float p1 = expf(l[i1] - l[i0]);
            float inv = 1.0f / (1.0f + p1);
            float w0 = inv, w1 = p1 * inv;
            gI[n] = make_int2(i0, i1);
            gW[n] = make_float2(w0, w1);
            if (i0 > 0) {
                int idx = atomicAdd(&cnt[i0 - 1], 1);
                lst[(i0 - 1) * M_CLS + idx] = n;
                wls[(i0 - 1) * M_CLS + idx] = w0;
            }
            if (i1 > 0) {
                int idx = atomicAdd(&cnt[i1 - 1], 1);
                lst[(i1 - 1) * M_CLS + idx] = n | (1 << 16);
                wls[(i1 - 1) * M_CLS + idx] = w1;
            }
        }
        return;
    }

    const float* W; __half* Wt; int K, N, tileIdx;
    if (bi < WT_W1)                   { W = W1;  Wt = w1t;  K = IN_DIM; N = HID;    tileIdx = bi; }
    else if ((bi -= WT_W1)  < WT_W2)  { W = W2;  Wt = w2t;  K = HID;    N = IN_DIM; tileIdx = bi; }
    else if ((bi -= WT_W2)  < WT_WIN) {
        int z = bi / WT_W1; tileIdx = bi - z * WT_W1;
        W = Win  + (size_t)z * IN_DIM * HID; Wt = wint  + (size_t)z * HID * IN_DIM;
        K = IN_DIM; N = HID;
    } else {
        bi -= WT_WIN;
        int z = bi / WT_W2; tileIdx = bi - z * WT_W2;
        W = Wout + (size_t)z * HID * IN_DIM; Wt = woutt + (size_t)z * IN_DIM * HID;
        K = HID; N = IN_DIM;
    }

    __shared__ float t[32][33];
    const int ktiles = K / 32;
    int k0 = (tileIdx % ktiles) * 32, n0 = (tileIdx / ktiles) * 32;
    int tx = threadIdx.x & 31, ty = threadIdx.x >> 5;
    #pragma unroll
    for (int i = 0; i < 4; i++)
        t[ty + i * 8][tx] = W[(size_t)(k0 + ty + i * 8) * N + n0 + tx];
    __syncthreads();
    #pragma unroll
    for (int it = 0; it < 2; it++) {
        int item = it * 256 + threadIdx.x;
        int n  = n0 + (item >> 4);
        int kp = (item & 15) * 2;
        __half2 hv;
        hv.x = __float2half(t[kp][item >> 4]);
        hv.y = __float2half(t[kp + 1][item >> 4]);
        *reinterpret_cast<__half2*>(Wt + (size_t)n * K + k0 + kp) = hv;
    }
}

// ---------------- final mix ----------------
__global__ __launch_bounds__(192)
void final_mix(const float* __restrict__ e0,
               const float* __restrict__ moeOut,
               const int2* __restrict__ gI,
               const float2* __restrict__ gW,
               float* __restrict__ out)
{
    const int n = blockIdx.x;
    const int b = n / NCLS;
    const int t = n - b * NCLS;
    int2  ii = gI[n];
    float2 ww = gW[n];
    const float* e0row = e0 + (size_t)n * IN_DIM;
    const float* m0 = moeOut + (size_t)(n * 2 + 0) * IN_DIM;
    const float* m1 = moeOut + (size_t)(n * 2 + 1) * IN_DIM;
    float* orow = out + (size_t)(b * SEQ + t) * IN_DIM;
    for (int c = threadIdx.x; c < IN_DIM; c += 192) {
        float v = (ii.x == 0) ? ww.x * e0row[c] : m0[c];
        v      += (ii.y == 0) ? ww.y * e0row[c] : m1[c];
        orow[c] = v;
    }
}

// ---------------- launch ----------------
extern "C" void kernel_launch(void* const* d_in, const int* in_sizes, int n_in,
                              void* d_out, int out_size)
{
    const float* x     = (const float*)d_in[0];
    const float* W1    = (const float*)d_in[1];
    const float* b1    = (const float*)d_in[2];
    const float* W2    = (const float*)d_in[3];
    const float* b2    = (const float*)d_in[4];
    const float* W_in  = (const float*)d_in[5];
    const float* b_in  = (const float*)d_in[6];
    const float* W_out = (const float*)d_in[7];
    const float* b_out = (const float*)d_in[8];
    const float* Wg    = (const float*)d_in[9];
    float* out = (float*)d_out;

    static __half *xh = nullptr, *w1t, *hid, *w2t, *wint, *woutt, *hm2;
    static float *e0, *moeOut, *wls;
    static int *cnt, *lst;
    static int2 *gI;
    static float2 *gW;
    if (!xh) {
        cudaGetSymbolAddress((void**)&xh,    g_xh);
        cudaGetSymbolAddress((void**)&w1t,   g_w1t);
        cudaGetSymbolAddress((void**)&hid,   g_hid);
        cudaGetSymbolAddress((void**)&w2t,   g_w2t);
        cudaGetSymbolAddress((void**)&wint,  g_wint);
        cudaGetSymbolAddress((void**)&woutt, g_woutt);
        cudaGetSymbolAddress((void**)&hm2,   g_hm2);
        cudaGetSymbolAddress((void**)&e0,    g_e0);
        cudaGetSymbolAddress((void**)&moeOut,g_moeOut);
        cudaGetSymbolAddress((void**)&cnt,   g_cnt);
        cudaGetSymbolAddress((void**)&lst,   g_lst);
        cudaGetSymbolAddress((void**)&wls,   g_wls);
        cudaGetSymbolAddress((void**)&gI,    g_gI);
        cudaGetSymbolAddress((void**)&gW,    g_gW);
        cudaFuncSetAttribute((const void*)fused_gemm<0>,
                             cudaFuncAttributeMaxDynamicSharedMemorySize, SMEM_DYN);
        cudaFuncSetAttribute((const void*)fused_gemm<1>,
                             cudaFuncAttributeMaxDynamicSharedMemorySize, SMEM_DYN);
    }

    // 0: reset expert counters
    cudaMemsetAsync(cnt, 0, ATOMS * sizeof(int));

    // 1: conversions + gating fused
    conv_all<<<CONV_TOTAL, 256>>>(x, xh, W1, w1t, W2, w2t, W_in, wint, W_out, woutt,
                                  Wg, cnt, lst, wls, gI, gW);

    // 2: phase A big GEMM + hm2 gather tiles in one grid
    fused_gemm<0><<<A_TOTAL, NTHREADS, SMEM_DYN>>>(
        xh, w1t, b1, hid, nullptr, nullptr,
        xh, wint, b_in, hm2, nullptr, cnt, lst, wls);

    // 3: phase B big GEMM + moeOut gather tiles in one grid
    fused_gemm<1><<<B_TOTAL, NTHREADS, SMEM_DYN>>>(
        hid, w2t, b2, nullptr, out, e0,
        hm2, woutt, b_out, nullptr, moeOut, cnt, lst, wls);

    // 4: final mix of cls rows
    final_mix<<<M_CLS, 192>>>(e0, moeOut, gI, gW, out);
}

// round 14
// speedup vs baseline: 1.1703x; 1.0064x over previous
#include <cuda_runtime.h>
#include <cuda_fp16.h>
#include <math.h>
#include <stdint.h>

// ---------------- problem constants ----------------
#define IN_DIM   768
#define HID      3072
#define BATCH    64
#define NCLS     6
#define NUM_PATCH 576
#define ATOMS    5
#define SEQ      (NCLS + NUM_PATCH)          // 582
#define M_PATCH  (BATCH * NUM_PATCH)         // 36864
#define M_CLS    (BATCH * NCLS)              // 384
#define M_ALL    (M_PATCH + M_CLS)           // 37248

// ---------------- device scratch ----------------
__device__ __half g_xh  [(size_t)M_ALL * IN_DIM];
__device__ __half g_w1t [(size_t)HID * IN_DIM];
__device__ __half g_hid [(size_t)M_ALL * HID];
__device__ __half g_w2t [(size_t)IN_DIM * HID];
__device__ __half g_wint [(size_t)ATOMS * HID * IN_DIM];
__device__ __half g_woutt[(size_t)ATOMS * IN_DIM * HID];
__device__ __half g_hm2 [(size_t)M_CLS * HID];
__device__ float g_e0  [(size_t)M_CLS * IN_DIM];
__device__ float g_moeOut[(size_t)M_CLS * 2 * IN_DIM];
__device__ int   g_cnt [ATOMS];                  // zero-init at load; final_mix re-zeroes
__device__ int   g_lst [ATOMS * M_CLS];
__device__ float g_wls [ATOMS * M_CLS];
__device__ int2  g_gI  [M_CLS];
__device__ float2 g_gW [M_CLS];

__device__ __forceinline__ float gelu_f(float v) {
    return 0.5f * v * (1.0f + erff(v * 0.7071067811865476f));
}

// ---------------- PTX helpers ----------------
__device__ __forceinline__ uint32_t smem_u32(const void* p) {
    uint32_t a;
    asm("{ .reg .u64 t; cvta.to.shared.u64 t, %1; cvt.u32.u64 %0, t; }" : "=r"(a) : "l"(p));
    return a;
}
__device__ __forceinline__ void cp16(uint32_t d, const void* s) {
    asm volatile("cp.async.cg.shared.global [%0], [%1], 16;" :: "r"(d), "l"(s));
}
#define CP_COMMIT()  asm volatile("cp.async.commit_group;" ::: "memory")
#define CP_WAIT(n)   asm volatile("cp.async.wait_group %0;" :: "n"(n) : "memory")

__device__ __forceinline__ void ldsm_x4(uint32_t& r0, uint32_t& r1, uint32_t& r2, uint32_t& r3,
                                        uint32_t addr) {
    asm volatile("ldmatrix.sync.aligned.m8n8.x4.shared.b16 {%0,%1,%2,%3}, [%4];"
                 : "=r"(r0), "=r"(r1), "=r"(r2), "=r"(r3) : "r"(addr));
}
__device__ __forceinline__ void mma_f16(float& c0, float& c1, float& c2, float& c3,
                                        uint32_t a0, uint32_t a1, uint32_t a2, uint32_t a3,
                                        uint32_t b0, uint32_t b1) {
    asm volatile("mma.sync.aligned.m16n8k16.row.col.f32.f16.f16.f32 "
                 "{%0,%1,%2,%3}, {%4,%5,%6,%7}, {%8,%9}, {%0,%1,%2,%3};"
                 : "+f"(c0), "+f"(c1), "+f"(c2), "+f"(c3)
                 : "r"(a0), "r"(a1), "r"(a2), "r"(a3), "r"(b0), "r"(b1));
}
__device__ __forceinline__ uint32_t sw128(uint32_t off) {
    return off ^ ((off >> 3) & 0x70);
}

// ---------------- fused GEMM (big path + gathered MoE path in one grid) ----------------
#define BM 128
#define BN 128
#define BK 64
#define STAGES 3
#define STG_BYTES (BM * 128)
#define SMEM_DYN (STAGES * 2 * STG_BYTES)        // 96 KB
#define NTHREADS 128

#define A_NBX    (HID / BN)                      // 24
#define A_NBIG   (A_NBX * (M_ALL / BM))          // 6984
#define B_NBX    (IN_DIM / BN)                   // 6
#define B_NBIG   (B_NBX * (M_ALL / BM))          // 1746

#define GBM 64
#define GBN 128
#define GSTG_A (GBM * 128)                       // 8 KB
#define GSTG_B (GBN * 128)                       // 16 KB
#define GSTG (GSTG_A + GSTG_B)                   // 24 KB
#define HM_BLOCKS  (6 * (HID / GBN))             // 144
#define MOE_BLOCKS (ATOMS * 6 * (IN_DIM / GBN))  // 180
#define A_TOTAL (A_NBIG + HM_BLOCKS)             // 7128
#define B_TOTAL (B_NBIG + MOE_BLOCKS)            // 1926

template<int PHASE>
__global__ __launch_bounds__(NTHREADS, 2)
void fused_gemm(const __half* __restrict__ A,
                const __half* __restrict__ Bw,
                const float* __restrict__ bias,
                __half* __restrict__ outH,
                float* __restrict__ outF,
                float* __restrict__ outE0,
                const __half* __restrict__ Ag,
                const __half* __restrict__ Wsm,
                const float* __restrict__ biasSm,
                __half* __restrict__ outGH,
                float* __restrict__ outGF,
                const int* __restrict__ cnt,
                const int* __restrict__ lst,
                const float* __restrict__ wls)
{
    extern __shared__ char smem[];
    const uint32_t sb = smem_u32(smem);
    const int tid  = threadIdx.x;
    const int wid  = tid >> 5, lane = tid & 31;
    const int NBIG = (PHASE == 0) ? A_NBIG : B_NBIG;
    const int K    = (PHASE == 0) ? IN_DIM : HID;
    const int C    = K >> 6;

    if (blockIdx.x < (unsigned)NBIG) {
        // ---------------- BIG PATH: 128x128 tile, 4 warps 2x2 ----------------
        const int wm = wid >> 1, wn = wid & 1;
        const int bi = blockIdx.x;
        const int NBX = (PHASE == 0) ? A_NBX : B_NBX;
        const int bm = (bi / NBX) * BM;
        const int bn = (bi % NBX) * BN;

        const __half* aG0 = A + (size_t)bm * K;
        const __half* bG0 = Bw + (size_t)bn * K;

        auto loadChunk = [&](int c) {
            const int slot = c % STAGES;
            const uint32_t aS = sb + (uint32_t)slot * (2 * STG_BYTES);
            const uint32_t bS = aS + STG_BYTES;
            const __half* aG = aG0 + c * BK;
            const __half* bG = bG0 + c * BK;
            #pragma unroll
            for (int t = 0; t < 8; t++) {
                int i = t * NTHREADS + tid;
                int row = i >> 3, g = i & 7;
                uint32_t off = (uint32_t)(row * 128 + g * 16);
                cp16(aS + sw128(off), aG + (size_t)row * K + g * 8);
            }
            #pragma unroll
            for (int t = 0; t < 8; t++) {
                int i = t * NTHREADS + tid;
                int row = i >> 3, g = i & 7;
                uint32_t off = (uint32_t)(row * 128 + g * 16);
                cp16(bS + sw128(off), bG + (size_t)row * K + g * 8);
            }
            CP_COMMIT();
        };

        float acc[4][8][4];
        #pragma unroll
        for (int i = 0; i < 4; i++)
            #pragma unroll
            for (int j = 0; j < 8; j++)
                #pragma unroll
                for (int q = 0; q < 4; q++) acc[i][j][q] = 0.0f;

        loadChunk(0);
        loadChunk(1);

        const int aRow = wm * 64 + (lane & 15);
        const int aCol = (lane >> 4) * 16;
        const int bRow = wn * 64 + ((lane >> 4) & 1) * 8 + (lane & 7);
        const int bCol = ((lane >> 3) & 1) * 16;

        for (int c = 0; c < C; c++) {
            if (c + 2 < C) { CP_WAIT(1); } else { CP_WAIT(0); }
            __syncthreads();
            if (c + 2 < C) loadChunk(c + 2);

            const int slot = c % STAGES;
            const uint32_t aS = sb + (uint32_t)slot * (2 * STG_BYTES);
            const uint32_t bS = aS + STG_BYTES;

            #pragma unroll
            for (int kk = 0; kk < 4; kk++) {
                uint32_t af[4][4];
                #pragma unroll
                for (int mt = 0; mt < 4; mt++) {
                    uint32_t off = (uint32_t)((aRow + mt * 16) * 128 + kk * 32 + aCol);
                    ldsm_x4(af[mt][0], af[mt][1], af[mt][2], af[mt][3], aS + sw128(off));
                }
                uint32_t bf[8][2];
                #pragma unroll
                for (int pr = 0; pr < 4; pr++) {
                    uint32_t off = (uint32_t)((bRow + pr * 16) * 128 + kk * 32 + bCol);
                    uint32_t r0, r1, r2, r3;
                    ldsm_x4(r0, r1, r2, r3, bS + sw128(off));
                    bf[pr * 2 + 0][0] = r0; bf[pr * 2 + 0][1] = r1;
                    bf[pr * 2 + 1][0] = r2; bf[pr * 2 + 1][1] = r3;
                }
                #pragma unroll
                for (int mt = 0; mt < 4; mt++)
                    #pragma unroll
                    for (int nt = 0; nt < 8; nt++)
                        mma_f16(acc[mt][nt][0], acc[mt][nt][1], acc[mt][nt][2], acc[mt][nt][3],
                                af[mt][0], af[mt][1], af[mt][2], af[mt][3],
                                bf[nt][0], bf[nt][1]);
            }
        }

        const int q = lane & 3;
        #pragma unroll
        for (int mt = 0; mt < 4; mt++) {
            #pragma unroll
            for (int h = 0; h < 2; h++) {
                const int rowg = bm + wm * 64 + mt * 16 + (lane >> 2) + h * 8;
                __half* rpH = nullptr;
                float*  rpF = nullptr;
                if (PHASE == 0) {
                    rpH = outH + (size_t)rowg * HID;
                } else {
                    if (rowg < M_PATCH) {
                        int bb = rowg / NUM_PATCH, p = rowg - bb * NUM_PATCH;
                        rpF = outF + (size_t)(bb * SEQ + NCLS + p) * IN_DIM;
                    } else {
                        rpF = outE0 + (size_t)(rowg - M_PATCH) * IN_DIM;
                    }
                }
                #pragma unroll
                for (int nt = 0; nt < 8; nt++) {
                    const int col = bn + wn * 64 + nt * 8 + q * 2;
                    float v0 = acc[mt][nt][h * 2 + 0] + bias[col];
                    float v1 = acc[mt][nt][h * 2 + 1] + bias[col + 1];
                    if (PHASE == 0) {
                        v0 = gelu_f(v0); v1 = gelu_f(v1);
                        __half2 hh; hh.x = __float2half(v0); hh.y = __float2half(v1);
                        *reinterpret_cast<__half2*>(rpH + col) = hh;
                    } else {
                        *reinterpret_cast<float2*>(rpF + col) = make_float2(v0, v1);
                    }
                }
            }
        }
    } else {
        // ---------------- GATHER PATH: 64x128 tile ----------------
        const int gbi = blockIdx.x - NBIG;
        const int wm = wid >> 1, wn = wid & 1;
        const int N = (PHASE == 0) ? HID : IN_DIM;

        int zsel, mtile, ntile;
        if (PHASE == 0) {
            const int nt = HID / GBN;
            int mslot = gbi / nt; ntile = gbi % nt;
            zsel  = (mslot <= 1) ? 0 : (mslot - 1);
            mtile = (mslot <= 1) ? mslot : 0;
        } else {
            zsel  = gbi / 36;
            int r = gbi % 36;
            mtile = r / 6; ntile = r % 6;
            if (mtile * GBM >= cnt[zsel]) return;
        }

        if (tid < GBM) {
            const __half* rp; int oi; float w = 1.0f;
            if (PHASE == 0) {
                int r = mtile * GBM + tid;
                int n = (zsel == 0) ? ((r < 64) ? r * 6 : (r - 64) * 6 + 5)
                                    : r * 6 + zsel;
                rp = Ag + (size_t)(M_PATCH + n) * IN_DIM;
                oi = n;
            } else {
                int r = mtile * GBM + tid;
                if (r < cnt[zsel]) {
                    int e = lst[zsel * M_CLS + r];
                    int n = e & 0xFFFF, s = e >> 16;
                    rp = Ag + (size_t)n * HID;
                    oi = n * 2 + s;
                    w  = wls[zsel * M_CLS + r];
                } else { rp = Ag; oi = -1; }
            }
            *reinterpret_cast<const __half**>(smem + tid * 8) = rp;
            reinterpret_cast<int*>(smem + 512)[tid]  = oi;
            reinterpret_cast<float*>(smem + 768)[tid] = w;
        }
        __syncthreads();

        const __half* bG0 = Wsm + (size_t)zsel * N * K + (size_t)(ntile * GBN) * K;
        const float* biasZ = biasSm + (size_t)zsel * N;

        auto loadChunkG = [&](int c) {
            const int slot = c % 3;
            const uint32_t aS = sb + 1024u + (uint32_t)slot * GSTG;
            const uint32_t bS = aS + GSTG_A;
            #pragma unroll
            for (int t = 0; t < 4; t++) {
                int i = t * 128 + tid;
                int row = i >> 3, g = i & 7;
                const __half* rp;
                asm("ld.shared.b64 %0, [%1];" : "=l"(rp) : "r"(sb + (uint32_t)(row * 8)));
                uint32_t off = (uint32_t)(row * 128 + g * 16);
                cp16(aS + sw128(off), rp + c * 64 + g * 8);
            }
            const __half* bG = bG0 + c * 64;
            #pragma unroll
            for (int t = 0; t < 8; t++) {
                int i = t * 128 + tid;
                int row = i >> 3, g = i & 7;
                uint32_t off = (uint32_t)(row * 128 + g * 16);
                cp16(bS + sw128(off), bG + (size_t)row * K + g * 8);
            }
            CP_COMMIT();
        };

        float acc[2][8][4];
        #pragma unroll
        for (int i = 0; i < 2; i++)
            #pragma unroll
            for (int j = 0; j < 8; j++)
                #pragma unroll
                for (int q = 0; q < 4; q++) acc[i][j][q] = 0.0f;

        loadChunkG(0);
        loadChunkG(1);

        const int aRow = wm * 32 + (lane & 15);
        const int aCol = (lane >> 4) * 16;
        const int bRow = wn * 64 + ((lane >> 4) & 1) * 8 + (lane & 7);
        const int bCol = ((lane >> 3) & 1) * 16;

        for (int c = 0; c < C; c++) {
            if (c + 2 < C) { CP_WAIT(1); } else { CP_WAIT(0); }
            __syncthreads();
            if (c + 2 < C) loadChunkG(c + 2);

            const int slot = c % 3;
            const uint32_t aS = sb + 1024u + (uint32_t)slot * GSTG;
            const uint32_t bS = aS + GSTG_A;

            #pragma unroll
            for (int kk = 0; kk < 4; kk++) {
                uint32_t af[2][4];
                #pragma unroll
                for (int mt = 0; mt < 2; mt++) {
                    uint32_t off = (uint32_t)((aRow + mt * 16) * 128 + kk * 32 + aCol);
                    ldsm_x4(af[mt][0], af[mt][1], af[mt][2], af[mt][3], aS + sw128(off));
                }
                uint32_t bf[8][2];
                #pragma unroll
                for (int pr = 0; pr < 4; pr++) {
                    uint32_t off = (uint32_t)((bRow + pr * 16) * 128 + kk * 32 + bCol);
                    uint32_t r0, r1, r2, r3;
                    ldsm_x4(r0, r1, r2, r3, bS + sw128(off));
                    bf[pr * 2 + 0][0] = r0; bf[pr * 2 + 0][1] = r1;
                    bf[pr * 2 + 1][0] = r2; bf[pr * 2 + 1][1] = r3;
                }
                #pragma unroll
                for (int mt = 0; mt < 2; mt++)
                    #pragma unroll
                    for (int nt = 0; nt < 8; nt++)
                        mma_f16(acc[mt][nt][0], acc[mt][nt][1], acc[mt][nt][2], acc[mt][nt][3],
                                af[mt][0], af[mt][1], af[mt][2], af[mt][3],
                                bf[nt][0], bf[nt][1]);
            }
        }

        const int q = lane & 3;
        #pragma unroll
        for (int mt = 0; mt < 2; mt++) {
            #pragma unroll
            for (int h = 0; h < 2; h++) {
                const int rowg = wm * 32 + mt * 16 + (lane >> 2) + h * 8;
                int   oi = reinterpret_cast<int*>(smem + 512)[rowg];
                float w  = reinterpret_cast<float*>(smem + 768)[rowg];
                #pragma unroll
                for (int nt = 0; nt < 8; nt++) {
                    const int col = ntile * GBN + wn * 64 + nt * 8 + q * 2;
                    float v0 = acc[mt][nt][h * 2 + 0] + biasZ[col];
                    float v1 = acc[mt][nt][h * 2 + 1] + biasZ[col + 1];
                    if (PHASE == 0) {
                        v0 = gelu_f(v0); v1 = gelu_f(v1);
                        __half2 hh; hh.x = __float2half(v0); hh.y = __float2half(v1);
                        *reinterpret_cast<__half2*>(outGH + (size_t)oi * HID + col) = hh;
                    } else if (oi >= 0) {
                        *reinterpret_cast<float2*>(outGF + (size_t)oi * IN_DIM + col)
                            = make_float2(w * v0, w * v1);
                    }
                }
            }
        }
    }
}

// ---------------- fused conversion + gating kernel ----------------
#define CX_BLK   (M_ALL * IN_DIM / 8 / 256)            // 13968 (8 elems/thread)
#define WT_W1    (IN_DIM / 32 * (HID / 32))
#define WT_W2    (HID / 32 * (IN_DIM / 32))
#define WT_WIN   (WT_W1 * ATOMS)
#define WT_WOUT  (WT_W2 * ATOMS)
#define CONV_BLOCKS (CX_BLK + WT_W1 + WT_W2 + WT_WIN + WT_WOUT)
#define CONV_TOTAL (CONV_BLOCKS + M_CLS)

__global__ __launch_bounds__(256)
void conv_all(const float* __restrict__ x,   __half* __restrict__ xh,
              const float* __restrict__ W1,  __half* __restrict__ w1t,
              const float* __restrict__ W2,  __half* __restrict__ w2t,
              const float* __restrict__ Win, __half* __restrict__ wint,
              const float* __restrict__ Wout,__half* __restrict__ woutt,
              const float* __restrict__ Wg,
              int* __restrict__ cnt, int* __restrict__ lst, float* __restrict__ wls,
              int2* __restrict__ gI, float2* __restrict__ gW)
{
    int bi = blockIdx.x;
    if (bi < CX_BLK) {
        int idx = bi * 256 + threadIdx.x;            // units of 8 elems
        int m  = idx / (IN_DIM / 8);
        int kp = (idx - m * (IN_DIM / 8)) * 8;
        int src;
        if (m < M_PATCH) { int b = m / NUM_PATCH, p = m - b * NUM_PATCH; src = b * SEQ + NCLS + p; }
        else             { int rr = m - M_PATCH; int b = rr / NCLS, t = rr - b * NCLS; src = b * SEQ + t; }
        const float* sp = x + (size_t)src * IN_DIM + kp;
        float4 v0 = *reinterpret_cast<const float4*>(sp);
        float4 v1 = *reinterpret_cast<const float4*>(sp + 4);
        __half2 h0; h0.x = __float2half(v0.x); h0.y = __float2half(v0.y);
        __half2 h1; h1.x = __float2half(v0.z); h1.y = __float2half(v0.w);
        __half2 h2; h2.x = __float2half(v1.x); h2.y = __float2half(v1.y);
        __half2 h3; h3.x = __float2half(v1.z); h3.y = __float2half(v1.w);
        uint4 pk;
        pk.x = *reinterpret_cast<uint32_t*>(&h0);
        pk.y = *reinterpret_cast<uint32_t*>(&h1);
        pk.z = *reinterpret_cast<uint32_t*>(&h2);
        pk.w = *reinterpret_cast<uint32_t*>(&h3);
        *reinterpret_cast<uint4*>(xh + (size_t)m * IN_DIM + kp) = pk;
        return;
    }
    bi -= CX_BLK;

    if (bi >= WT_W1 + WT_W2 + WT_WIN + WT_WOUT) {
        // ---- gating block: one per cls token ----
        const int n = bi - (WT_W1 + WT_W2 + WT_WIN + WT_WOUT);
        const int b = n / NCLS;
        const int t = n - b * NCLS;

        __shared__ float scls[IN_DIM];
        __shared__ float slog[6];

        const float* crow = x + (size_t)(b * SEQ + t) * IN_DIM;
        for (int i = threadIdx.x; i < IN_DIM; i += 256) scls[i] = crow[i];
        __syncthreads();

        const int w = threadIdx.x >> 5, lane = threadIdx.x & 31;
        if (w < 6) {
            const float* wg = Wg + (size_t)t * IN_DIM * 6;
            float s = 0.0f;
            for (int d = lane; d < IN_DIM; d += 32)
                s = fmaf(scls[d], wg[(size_t)d * 6 + w], s);
            #pragma unroll
            for (int off = 16; off > 0; off >>= 1)
                s += __shfl_down_sync(0xffffffffu, s, off);
            if (lane == 0) slog[w] = s;
        }
        __syncthreads();

        if (threadIdx.x == 0) {
            float l[6];
            #pragma unroll
            for (int j = 0; j < 6; j++) l[j] = slog[j];
            int i0 = 0;
            #pragma unroll
            for (int j = 1; j < 6; j++) if (l[j] > l[i0]) i0 = j;
            int i1 = (i0 == 0) ? 1 : 0;
            #pragma unroll
            for (int j = 0; j < 6; j++) if (j != i0 && l[j] > l[i1]) i1 = j;
            float p1 = expf(l[i1] - l[i0]);
            float inv = 1.0f / (1.0f + p1);
            float w0 = inv, w1 = p1 * inv;
            gI[n] = make_int2(i0, i1);
            gW[n] = make_float2(w0, w1);
            if (i0 > 0) {
                int idx = atomicAdd(&cnt[i0 - 1], 1);
                lst[(i0 - 1) * M_CLS + idx] = n;
                wls[(i0 - 1) * M_CLS + idx] = w0;
            }
            if (i1 > 0) {
                int idx = atomicAdd(&cnt[i1 - 1], 1);
                lst[(i1 - 1) * M_CLS + idx] = n | (1 << 16);
                wls[(i1 - 1) * M_CLS + idx] = w1;
            }
        }
        return;
    }

    const float* W; __half* Wt; int K, N, tileIdx;
    if (bi < WT_W1)                   { W = W1;  Wt = w1t;  K = IN_DIM; N = HID;    tileIdx = bi; }
    else if ((bi -= WT_W1)  < WT_W2)  { W = W2;  Wt = w2t;  K = HID;    N = IN_DIM; tileIdx = bi; }
    else if ((bi -= WT_W2)  < WT_WIN) {
        int z = bi / WT_W1; tileIdx = bi - z * WT_W1;
        W = Win  + (size_t)z * IN_DIM * HID; Wt = wint  + (size_t)z * HID * IN_DIM;
        K = IN_DIM; N = HID;
    } else {
        bi -= WT_WIN;
        int z = bi / WT_W2; tileIdx = bi - z * WT_W2;
        W = Wout + (size_t)z * HID * IN_DIM; Wt = woutt + (size_t)z * IN_DIM * HID;
        K = HID; N = IN_DIM;
    }

    __shared__ float t[32][33];
    const int ktiles = K / 32;
    int k0 = (tileIdx % ktiles) * 32, n0 = (tileIdx / ktiles) * 32;
    int tx = threadIdx.x & 31, ty = threadIdx.x >> 5;
    #pragma unroll
    for (int i = 0; i < 4; i++)
        t[ty + i * 8][tx] = W[(size_t)(k0 + ty + i * 8) * N + n0 + tx];
    __syncthreads();
    #pragma unroll
    for (int it = 0; it < 2; it++) {
        int item = it * 256 + threadIdx.x;
        int n  = n0 + (item >> 4);
        int kp = (item & 15) * 2;
        __half2 hv;
        hv.x = __float2half(t[kp][item >> 4]);
        hv.y = __float2half(t[kp + 1][item >> 4]);
        *reinterpret_cast<__half2*>(Wt + (size_t)n * K + k0 + kp) = hv;
    }
}

// ---------------- final mix (+ counter reset for next replay) ----------------
__global__ __launch_bounds__(192)
void final_mix(const float* __restrict__ e0,
               const float* __restrict__ moeOut,
               const int2* __restrict__ gI,
               const float2* __restrict__ gW,
               float* __restrict__ out,
               int* __restrict__ cnt)
{
    const int n = blockIdx.x;
    const int b = n / NCLS;
    const int t = n - b * NCLS;
    int2  ii = gI[n];
    float2 ww = gW[n];
    const float* e0row = e0 + (size_t)n * IN_DIM;
    const float* m0 = moeOut + (size_t)(n * 2 + 0) * IN_DIM;
    const float* m1 = moeOut + (size_t)(n * 2 + 1) * IN_DIM;
    float* orow = out + (size_t)(b * SEQ + t) * IN_DIM;
    for (int c = threadIdx.x; c < IN_DIM; c += 192) {
        float v = (ii.x == 0) ? ww.x * e0row[c] : m0[c];
        v      += (ii.y == 0) ? ww.y * e0row[c] : m1[c];
        orow[c] = v;
    }
    // reset expert counters for the next call (globals start zero-initialized,
    // and every call ends with cnt == 0 -> deterministic across graph replays)
    if (blockIdx.x == 0 && threadIdx.x < ATOMS) cnt[threadIdx.x] = 0;
}

// ---------------- launch ----------------
extern "C" void kernel_launch(void* const* d_in, const int* in_sizes, int n_in,
                              void* d_out, int out_size)
{
    const float* x     = (const float*)d_in[0];
    const float* W1    = (const float*)d_in[1];
    const float* b1    = (const float*)d_in[2];
    const float* W2    = (const float*)d_in[3];
    const float* b2    = (const float*)d_in[4];
    const float* W_in  = (const float*)d_in[5];
    const float* b_in  = (const float*)d_in[6];
    const float* W_out = (const float*)d_in[7];
    const float* b_out = (const float*)d_in[8];
    const float* Wg    = (const float*)d_in[9];
    float* out = (float*)d_out;

    static __half *xh = nullptr, *w1t, *hid, *w2t, *wint, *woutt, *hm2;
    static float *e0, *moeOut, *wls;
    static int *cnt, *lst;
    static int2 *gI;
    static float2 *gW;
    if (!xh) {
        cudaGetSymbolAddress((void**)&xh,    g_xh);
        cudaGetSymbolAddress((void**)&w1t,   g_w1t);
        cudaGetSymbolAddress((void**)&hid,   g_hid);
        cudaGetSymbolAddress((void**)&w2t,   g_w2t);
        cudaGetSymbolAddress((void**)&wint,  g_wint);
        cudaGetSymbolAddress((void**)&woutt, g_woutt);
        cudaGetSymbolAddress((void**)&hm2,   g_hm2);
        cudaGetSymbolAddress((void**)&e0,    g_e0);
        cudaGetSymbolAddress((void**)&moeOut,g_moeOut);
        cudaGetSymbolAddress((void**)&cnt,   g_cnt);
        cudaGetSymbolAddress((void**)&lst,   g_lst);
        cudaGetSymbolAddress((void**)&wls,   g_wls);
        cudaGetSymbolAddress((void**)&gI,    g_gI);
        cudaGetSymbolAddress((void**)&gW,    g_gW);
        cudaFuncSetAttribute((const void*)fused_gemm<0>,
                             cudaFuncAttributeMaxDynamicSharedMemorySize, SMEM_DYN);
        cudaFuncSetAttribute((const void*)fused_gemm<1>,
                             cudaFuncAttributeMaxDynamicSharedMemorySize, SMEM_DYN);
    }

    // 1: conversions + gating fused (cnt is 0 on entry: zero-init / reset by final_mix)
    conv_all<<<CONV_TOTAL, 256>>>(x, xh, W1, w1t, W2, w2t, W_in, wint, W_out, woutt,
                                  Wg, cnt, lst, wls, gI, gW);

    // 2: phase A big GEMM + hm2 gather tiles
    fused_gemm<0><<<A_TOTAL, NTHREADS, SMEM_DYN>>>(
        xh, w1t, b1, hid, nullptr, nullptr,
        xh, wint, b_in, hm2, nullptr, cnt, lst, wls);

    // 3: phase B big GEMM + moeOut gather tiles
    fused_gemm<1><<<B_TOTAL, NTHREADS, SMEM_DYN>>>(
        hid, w2t, b2, nullptr, out, e0,
        hm2, woutt, b_out, nullptr, moeOut, cnt, lst, wls);

    // 4: final mix + counter reset
    final_mix<<<M_CLS, 192>>>(e0, moeOut, gI, gW, out, cnt);
}